// round 5
// baseline (speedup 1.0000x reference)
#include <cuda_runtime.h>
#include <math.h>

#define Bq 8
#define Tq 4096
#define Dq 896
#define Sq 64
#define Cq 128
#define NCq 32

#define GM (Bq*Tq)
#define GN Dq
#define GK Dq

// ---------------- global scratch ----------------
__device__ float g_G[Bq][NCq][Cq][Cq];        // self grams H_c H_c^T
__device__ float g_Gx[Bq][NCq][Cq][Cq];       // cross grams H_{c+1} H_c^T
__device__ float g_hd[Bq][Tq][4];             // h.Wnm_h, h.Wnm_m, h.Wwg_h, (pad)
__device__ float g_Ball[NCq][Bq][Sq][Dq];     // base memory at start of each chunk
__device__ float g_P[Bq][Cq][Sq];             // h_{c,t} . B_c[s]
__device__ float g_P0[Bq][Cq][Sq];            // h_{c+1,t} . B_c[s]
__device__ float g_u[Bq][Sq];                 // B_c[s] . Wnm_m (+ accumulated)
__device__ float g_beta[Bq][NCq][Cq][Sq];
__device__ float g_gamma[Bq][NCq][Cq][Cq];
__device__ float g_afinC[NCq][Bq][Sq];
__device__ float g_kapC[NCq][Bq][Cq];
__device__ int   g_idxC[NCq][Bq][Cq];
__device__ int   g_cnt[Bq];
__device__ float g_m[(size_t)Bq*Tq*Dq];
__device__ float g_stats[(size_t)Bq*Tq][2];

// smem layout for chunk_kernel (float offsets)
#define OF_G    0        // 16384
#define OF_GX   16384    // 16384
#define OF_P    32768    // 8192
#define OF_HD   40960    // 512 (float4[128])
#define OF_KAP  41472    // 128
#define OF_IDX  41600    // 128 (int)
#define OF_ESM  41728    // 64
#define OF_MSK  41792    // 256 (uint 64x4)
#define OF_AF   42048    // 64
#define OF_U    42112    // 64
#define SMEM_FLOATS 42176
#define SMEM_BYTES (SMEM_FLOATS*4)

__device__ __forceinline__ unsigned okey(float f) {
    unsigned u = __float_as_uint(f);
    return (u & 0x80000000u) ? ~u : (u | 0x80000000u);
}
__device__ __forceinline__ float dekey(unsigned k) {
    unsigned u = (k & 0x80000000u) ? (k ^ 0x80000000u) : ~k;
    return __uint_as_float(u);
}

// ---------------------------------------------------------------------
__global__ void init_kernel() {
    int tid = blockIdx.x * blockDim.x + threadIdx.x;
    int stride = gridDim.x * blockDim.x;
    int nb = Bq * Sq * Dq;
    for (int i = tid; i < nb; i += stride) (&g_Ball[0][0][0][0])[i] = 0.f;
    int np = Bq * Cq * Sq;
    for (int i = tid; i < np; i += stride) {
        (&g_P[0][0][0])[i] = 0.f;
        (&g_P0[0][0][0])[i] = 0.f;
    }
    if (tid < Bq * Sq) (&g_u[0][0])[tid] = 0.f;
    if (tid < Bq) g_cnt[tid] = 0;
}

// ---------------------------------------------------------------------
// pre: blocks [0,256): G[b][c] = Hc Hc^T  (+ h-dot vectors)
//      blocks [256,504): Gx[b][c] = H_{c+1} Hc^T
// ---------------------------------------------------------------------
__global__ __launch_bounds__(256) void pre_kernel(
    const float* __restrict__ h,
    const float* __restrict__ W_nm,
    const float* __restrict__ W_wg)
{
    __shared__ float As[8][128];
    __shared__ float Bs[8][128];

    const int tid = threadIdx.x;
    const int tr = tid >> 4, tc = tid & 15;
    const int lr = tid >> 1, lk = (tid & 1) * 4;

    int b, c;
    const float *Arow, *Brow;
    float* outp;
    bool doHd;
    if (blockIdx.x < Bq * NCq) {
        b = blockIdx.x / NCq; c = blockIdx.x % NCq;
        Arow = h + ((size_t)b * Tq + c * Cq) * Dq;
        Brow = Arow;
        outp = &g_G[b][c][0][0];
        doHd = true;
    } else {
        int k = blockIdx.x - Bq * NCq;
        b = k / (NCq - 1); c = k % (NCq - 1);
        Arow = h + ((size_t)b * Tq + (c + 1) * Cq) * Dq;
        Brow = h + ((size_t)b * Tq + c * Cq) * Dq;
        outp = &g_Gx[b][c][0][0];
        doHd = false;
    }

    float acc[8][8];
    #pragma unroll
    for (int i = 0; i < 8; ++i)
        #pragma unroll
        for (int j = 0; j < 8; ++j) acc[i][j] = 0.f;

    float4 av = *(const float4*)(Arow + (size_t)lr * Dq + lk);
    float4 bv = *(const float4*)(Brow + (size_t)lr * Dq + lk);
    for (int k0 = 0; k0 < Dq; k0 += 8) {
        __syncthreads();
        As[lk + 0][lr] = av.x; As[lk + 1][lr] = av.y;
        As[lk + 2][lr] = av.z; As[lk + 3][lr] = av.w;
        Bs[lk + 0][lr] = bv.x; Bs[lk + 1][lr] = bv.y;
        Bs[lk + 2][lr] = bv.z; Bs[lk + 3][lr] = bv.w;
        __syncthreads();
        if (k0 + 8 < Dq) {
            av = *(const float4*)(Arow + (size_t)lr * Dq + k0 + 8 + lk);
            bv = *(const float4*)(Brow + (size_t)lr * Dq + k0 + 8 + lk);
        }
        #pragma unroll
        for (int kk = 0; kk < 8; ++kk) {
            float a[8], bb[8];
            #pragma unroll
            for (int i = 0; i < 8; ++i) a[i]  = As[kk][tr + 16 * i];
            #pragma unroll
            for (int j = 0; j < 8; ++j) bb[j] = Bs[kk][tc + 16 * j];
            #pragma unroll
            for (int i = 0; i < 8; ++i)
                #pragma unroll
                for (int j = 0; j < 8; ++j)
                    acc[i][j] = fmaf(a[i], bb[j], acc[i][j]);
        }
    }
    #pragma unroll
    for (int i = 0; i < 8; ++i)
        #pragma unroll
        for (int j = 0; j < 8; ++j)
            outp[(tr + 16 * i) * Cq + tc + 16 * j] = acc[i][j];

    if (doHd) {
        const int w = tid >> 5, l = tid & 31;
        const int t0 = c * Cq;
        for (int r = w; r < Cq; r += 8) {
            const float* hr = Arow + (size_t)r * Dq;
            float s0 = 0.f, s1 = 0.f, s2 = 0.f;
            for (int d = l; d < Dq; d += 32) {
                float x = hr[d];
                s0 += x * W_nm[d];
                s1 += x * W_nm[Dq + d];
                s2 += x * W_wg[d];
            }
            #pragma unroll
            for (int o = 16; o > 0; o >>= 1) {
                s0 += __shfl_xor_sync(0xffffffffu, s0, o);
                s1 += __shfl_xor_sync(0xffffffffu, s1, o);
                s2 += __shfl_xor_sync(0xffffffffu, s2, o);
            }
            if (l == 0) {
                g_hd[b][t0 + r][0] = s0;
                g_hd[b][t0 + r][1] = s1;
                g_hd[b][t0 + r][2] = s2;
                g_hd[b][t0 + r][3] = 0.f;
            }
        }
    }
}

// ---------------------------------------------------------------------
// chunk launch c:
//   blocks 0..7  : scan(c) in smem (warp0), then sparse fixup -> P(c+1)
//   blocks 8..71 : (no wait) build B_c from scan(c-1) state, then
//                  P0 = H_{c+1} . B_c, bump counter
// ---------------------------------------------------------------------
__global__ __launch_bounds__(256) void chunk_kernel(
    const float* __restrict__ h, const int* __restrict__ mask,
    const float* __restrict__ b_nm, const float* __restrict__ W_wg,
    const float* __restrict__ b_wg, int c)
{
    extern __shared__ float sm[];
    const int tid = threadIdx.x;

    if (blockIdx.x < 8) {
        float*    sG   = sm + OF_G;
        float*    sGx  = sm + OF_GX;
        float*    sP   = sm + OF_P;
        float4*   sHd  = (float4*)(sm + OF_HD);
        float*    kapS = sm + OF_KAP;
        int*      idxS = (int*)(sm + OF_IDX);
        float*    esm  = sm + OF_ESM;
        unsigned* mskS = (unsigned*)(sm + OF_MSK);
        float*    afS  = sm + OF_AF;
        float*    sU   = sm + OF_U;

        const int b = blockIdx.x;
        const int t0 = c * Cq;

        // stage
        const float4* gsrc = (const float4*)&g_G[b][c][0][0];
        for (int i = tid; i < Cq * Cq / 4; i += 256) ((float4*)sG)[i] = gsrc[i];
        const float4* psrc = (const float4*)&g_P[b][0][0];
        for (int i = tid; i < Cq * Sq / 4; i += 256) ((float4*)sP)[i] = psrc[i];
        if (tid < Cq) {
            float4 hv = ((const float4*)g_hd)[(size_t)b * Tq + t0 + tid];
            hv.w = (float)mask[b * Tq + t0 + tid];
            sHd[tid] = hv;
        }
        if (tid < Sq) sU[tid] = g_u[b][tid];
        if (tid < Cq) { kapS[tid] = 0.f; idxS[tid] = 0; }
        __syncthreads();

        if (tid < 32) {
            // ---------------- the scan (warp 0) ----------------
            const int l = tid;
            const float scale = rsqrtf((float)Dq);
            const float wwg_g = W_wg[Dq];
            const float bnm = b_nm[0], bwg = b_wg[0];
            float a0 = 1.f, a1 = 1.f;
            float u0 = sU[l], u1 = sU[l + 32];
            float U20 = 0.f, U21 = 0.f;
            unsigned m0[4] = {0, 0, 0, 0}, m1[4] = {0, 0, 0, 0};
            float* bet = &g_beta[b][c][0][0];
            float* gam = &g_gamma[b][c][0][0];

            for (int t = 0; t < Cq; ++t) {
                const float* gr = sG + t * Cq;
                float c0 = 0.f, c1 = 0.f;
                #pragma unroll
                for (int w2 = 0; w2 < 4; ++w2) {
                    unsigned wd = m0[w2];
                    while (wd) {
                        int bp = __ffs(wd) - 1; wd &= wd - 1;
                        int j = w2 * 32 + bp;
                        c0 = fmaf(kapS[j], gr[j], c0);
                    }
                    wd = m1[w2];
                    while (wd) {
                        int bp = __ffs(wd) - 1; wd &= wd - 1;
                        int j = w2 * 32 + bp;
                        c1 = fmaf(kapS[j], gr[j], c1);
                    }
                }
                float s0 = fmaf(a0, sP[t * Sq + l], c0) * scale;
                float s1 = fmaf(a1, sP[t * Sq + l + 32], c1) * scale;

                unsigned k0 = okey(s0), k1 = okey(s1);
                unsigned kmx = __reduce_max_sync(0xffffffffu, k0 > k1 ? k0 : k1);
                float mx = dekey(kmx);
                unsigned cand = (k0 == kmx) ? (unsigned)l
                              : (k1 == kmx) ? (unsigned)(l + 32) : 1000u;
                int mi = (int)__reduce_min_sync(0xffffffffu, cand);

                float e0 = __expf(s0 - mx), e1 = __expf(s1 - mx);
                esm[l] = e0; esm[l + 32] = e1;
                __syncwarp();

                float pe = e0 + e1;
                float pd = e0 * fmaf(a0, u0, U20) + e1 * fmaf(a1, u1, U21);
                #pragma unroll
                for (int o = 16; o > 0; o >>= 1) {
                    pe += __shfl_xor_sync(0xffffffffu, pe, o);
                    pd += __shfl_xor_sync(0xffffffffu, pd, o);
                }
                float inv = 1.f / pe;
                float mdot = pd * inv;

                float4 hdt = sHd[t];
                float gg = 1.f / (1.f + __expf(-(hdt.x + mdot + bnm)));
                float wg = 1.f / (1.f + __expf(-(hdt.z + gg * wwg_g + bwg)));
                wg = fminf(wg, 0.2f) * hdt.w;

                bet[t * Sq + l]      = e0 * inv * a0;
                bet[t * Sq + l + 32] = e1 * inv * a1;
                #pragma unroll
                for (int q = 0; q < 4; ++q) {
                    int j = l + 32 * q;
                    float gv = 0.f;
                    if (j < t) gv = esm[idxS[j]] * inv * kapS[j];
                    gam[t * Cq + j] = gv;
                }
                __syncwarp();   // gamma reads of kapS done before decay

                float dec = 1.f - wg;
                float vjt = hdt.y;
                if (mi == l) {
                    #pragma unroll
                    for (int w2 = 0; w2 < 4; ++w2) {
                        unsigned wd = m0[w2];
                        while (wd) {
                            int bp = __ffs(wd) - 1; wd &= wd - 1;
                            kapS[w2 * 32 + bp] *= dec;
                        }
                    }
                    a0 *= dec;
                    U20 = fmaf(U20, dec, wg * vjt);
                    m0[t >> 5] |= 1u << (t & 31);
                    kapS[t] = wg; idxS[t] = mi;
                } else if (mi == l + 32) {
                    #pragma unroll
                    for (int w2 = 0; w2 < 4; ++w2) {
                        unsigned wd = m1[w2];
                        while (wd) {
                            int bp = __ffs(wd) - 1; wd &= wd - 1;
                            kapS[w2 * 32 + bp] *= dec;
                        }
                    }
                    a1 *= dec;
                    U21 = fmaf(U21, dec, wg * vjt);
                    m1[t >> 5] |= 1u << (t & 31);
                    kapS[t] = wg; idxS[t] = mi;
                }
                __syncwarp();   // kapS/idxS updates visible next step
            }

            // epilogue
            g_u[b][l]      = fmaf(a0, u0, U20);
            g_u[b][l + 32] = fmaf(a1, u1, U21);
            afS[l] = a0; afS[l + 32] = a1;
            #pragma unroll
            for (int w2 = 0; w2 < 4; ++w2) {
                mskS[l * 4 + w2] = m0[w2];
                mskS[(l + 32) * 4 + w2] = m1[w2];
            }
            g_afinC[c][b][l] = a0; g_afinC[c][b][l + 32] = a1;
            #pragma unroll
            for (int q = 0; q < 4; ++q) {
                int j = l + 32 * q;
                g_kapC[c][b][j] = kapS[j];
                g_idxC[c][b][j] = idxS[j];
            }
        } else {
            // warps 1..7: stage Gx for the fixup while warp 0 scans
            if (c < NCq - 1) {
                const float4* xsrc = (const float4*)&g_Gx[b][c][0][0];
                for (int i = tid - 32; i < Cq * Cq / 4; i += 224)
                    ((float4*)sGx)[i] = xsrc[i];
            }
        }
        __syncthreads();

        if (c < NCq - 1) {
            if (tid == 0) {
                volatile int* vc = (volatile int*)&g_cnt[0];
                while (vc[b] < 8 * (c + 1)) {}
                __threadfence();
            }
            __syncthreads();
            // fixup: P(c+1)[t][s] = afin_s * P0[t][s] + sum_{j in slot s} kap_j * Gx[t][j]
            const int t = tid >> 1, base = (tid & 1) * 32;
            const float* P0r = &g_P0[b][t][0];
            const float* gxr = sGx + t * Cq;
            float* Pr = &g_P[b][t][0];
            for (int q = 0; q < 32; ++q) {
                int s = base + q;
                float v = afS[s] * P0r[s];
                #pragma unroll
                for (int w2 = 0; w2 < 4; ++w2) {
                    unsigned wd = mskS[s * 4 + w2];
                    while (wd) {
                        int bp = __ffs(wd) - 1; wd &= wd - 1;
                        int j = w2 * 32 + bp;
                        v = fmaf(kapS[j], gxr[j], v);
                    }
                }
                Pr[s] = v;
            }
        }
    } else {
        // -------- B path: build B_c, then P0 = H_{c+1} . B_c --------
        const int id = blockIdx.x - 8;
        const int b = id >> 3, s0 = (id & 7) * 8;

        if (c == 0) {
            // B_0 = 0 (init), P0 = 0 (init): just bump
            if (tid == 0) { __threadfence(); atomicAdd(&g_cnt[b], 1); }
            return;
        }

        float* kap2 = sm;              // [128]
        int*   idx2 = (int*)(sm + 128);
        float* af2  = sm + 256;        // [8]
        if (tid < Cq) { kap2[tid] = g_kapC[c - 1][b][tid]; idx2[tid] = g_idxC[c - 1][b][tid]; }
        if (tid < 8)  af2[tid] = g_afinC[c - 1][b][s0 + tid];
        __syncthreads();

        const int w = tid >> 5, l = tid & 31;
        const float* Hp = h + ((size_t)b * Tq + (c - 1) * Cq) * Dq;
        {
            const int s = s0 + w;
            const float4* Bo = (const float4*)&g_Ball[c - 1][b][s][0];
            float4*       Bn = (float4*)&g_Ball[c][b][s][0];
            const float as = af2[w];
            float4 acc[7];
            #pragma unroll
            for (int q = 0; q < 7; ++q) {
                float4 v = Bo[q * 32 + l];
                acc[q] = make_float4(as * v.x, as * v.y, as * v.z, as * v.w);
            }
            for (int j = 0; j < Cq; ++j) {
                if (idx2[j] == s) {
                    float kj = kap2[j];
                    const float4* hjp = (const float4*)(Hp + (size_t)j * Dq);
                    #pragma unroll
                    for (int q = 0; q < 7; ++q) {
                        float4 hv = hjp[q * 32 + l];
                        acc[q].x += kj * hv.x; acc[q].y += kj * hv.y;
                        acc[q].z += kj * hv.z; acc[q].w += kj * hv.w;
                    }
                }
            }
            #pragma unroll
            for (int q = 0; q < 7; ++q) Bn[q * 32 + l] = acc[q];
        }
        __syncthreads();

        if (c < NCq - 1) {
            // P0[t][s] = h_{c+1,t} . B_c[s]
            const int t = tid >> 1, sh = (tid & 1) * 4;
            const float4* Hn = (const float4*)(h + ((size_t)b * Tq + (c + 1) * Cq + t) * Dq);
            const float4* B0 = (const float4*)&g_Ball[c][b][s0 + sh + 0][0];
            const float4* B1 = (const float4*)&g_Ball[c][b][s0 + sh + 1][0];
            const float4* B2 = (const float4*)&g_Ball[c][b][s0 + sh + 2][0];
            const float4* B3 = (const float4*)&g_Ball[c][b][s0 + sh + 3][0];
            float a0 = 0.f, a1 = 0.f, a2 = 0.f, a3 = 0.f;
            #pragma unroll 4
            for (int k = 0; k < Dq / 4; ++k) {
                float4 hv = Hn[k];
                float4 x;
                x = B0[k]; a0 += hv.x * x.x + hv.y * x.y + hv.z * x.z + hv.w * x.w;
                x = B1[k]; a1 += hv.x * x.x + hv.y * x.y + hv.z * x.z + hv.w * x.w;
                x = B2[k]; a2 += hv.x * x.x + hv.y * x.y + hv.z * x.z + hv.w * x.w;
                x = B3[k]; a3 += hv.x * x.x + hv.y * x.y + hv.z * x.z + hv.w * x.w;
            }
            g_P0[b][t][s0 + sh + 0] = a0;
            g_P0[b][t][s0 + sh + 1] = a1;
            g_P0[b][t][s0 + sh + 2] = a2;
            g_P0[b][t][s0 + sh + 3] = a3;
            __syncthreads();
            if (tid == 0) { __threadfence(); atomicAdd(&g_cnt[b], 1); }
        }
    }
}

// ---------------------------------------------------------------------
// m-build over ALL chunks: m = [beta|gamma] @ [B_c ; H_c]
// ---------------------------------------------------------------------
__global__ __launch_bounds__(256) void mbuild_kernel(const float* __restrict__ h)
{
    __shared__ float As2[8][128];
    __shared__ float Bs[8][128];

    const int cc = blockIdx.x / 56;
    const int r  = blockIdx.x % 56;
    const int b  = r / 7;
    const int n0 = (r % 7) * 128;
    const int t0 = cc * Cq;
    const int tid = threadIdx.x;

    const float* Bold = &g_Ball[cc][b][0][0];
    const float* Hc = h + ((size_t)b * Tq + t0) * Dq;
    const float* bet = &g_beta[b][cc][0][0];
    const float* gam = &g_gamma[b][cc][0][0];

    const int tr = tid >> 4, tc = tid & 15;
    const int lr = tid >> 1, lk = (tid & 1) * 4;
    const int kr = tid >> 5, nc = (tid & 31) * 4;

    float acc[8][8];
    #pragma unroll
    for (int i = 0; i < 8; ++i)
        #pragma unroll
        for (int j = 0; j < 8; ++j) acc[i][j] = 0.f;

    for (int k0 = 0; k0 < Sq + Cq; k0 += 8) {
        float4 av = (k0 < Sq)
            ? *(const float4*)(bet + lr * Sq + k0 + lk)
            : *(const float4*)(gam + lr * Cq + k0 - Sq + lk);
        int kg = k0 + kr;
        const float* rp = (kg < Sq) ? (Bold + (size_t)kg * Dq)
                                    : (Hc + (size_t)(kg - Sq) * Dq);
        float4 bv = *(const float4*)(rp + n0 + nc);
        __syncthreads();
        As2[lk + 0][lr] = av.x; As2[lk + 1][lr] = av.y;
        As2[lk + 2][lr] = av.z; As2[lk + 3][lr] = av.w;
        Bs[kr][nc + 0] = bv.x; Bs[kr][nc + 1] = bv.y;
        Bs[kr][nc + 2] = bv.z; Bs[kr][nc + 3] = bv.w;
        __syncthreads();
        #pragma unroll
        for (int kk = 0; kk < 8; ++kk) {
            float a[8], bb[8];
            #pragma unroll
            for (int i = 0; i < 8; ++i) a[i]  = As2[kk][tr + 16 * i];
            #pragma unroll
            for (int j = 0; j < 8; ++j) bb[j] = Bs[kk][tc + 16 * j];
            #pragma unroll
            for (int i = 0; i < 8; ++i)
                #pragma unroll
                for (int j = 0; j < 8; ++j)
                    acc[i][j] = fmaf(a[i], bb[j], acc[i][j]);
        }
    }
    #pragma unroll
    for (int i = 0; i < 8; ++i) {
        size_t row = (size_t)b * Tq + t0 + tr + 16 * i;
        #pragma unroll
        for (int j = 0; j < 8; ++j)
            g_m[row * Dq + n0 + tc + 16 * j] = acc[i][j];
    }
}

// ---------------------------------------------------------------------
__global__ __launch_bounds__(256) void stats_kernel() {
    int row = blockIdx.x * 8 + (threadIdx.x >> 5);
    int l = threadIdx.x & 31;
    const float* mr = g_m + (size_t)row * Dq;
    float s = 0.f, s2 = 0.f;
    for (int d = l; d < Dq; d += 32) { float v = mr[d]; s += v; s2 += v * v; }
    #pragma unroll
    for (int o = 16; o > 0; o >>= 1) {
        s  += __shfl_xor_sync(0xffffffffu, s, o);
        s2 += __shfl_xor_sync(0xffffffffu, s2, o);
    }
    if (l == 0) {
        float mu = s * (1.f / (float)Dq);
        float var = s2 * (1.f / (float)Dq) - mu * mu;
        g_stats[row][0] = mu;
        g_stats[row][1] = rsqrtf(var + 1e-5f);
    }
}

// ---------------------------------------------------------------------
__global__ __launch_bounds__(256) void gemm_kernel(
    const float* __restrict__ Wt,
    const float* __restrict__ H,
    const float* __restrict__ lng,
    const float* __restrict__ lnb,
    float* __restrict__ C)
{
    __shared__ float As[8][128];
    __shared__ float Bs[8][128];

    const int bm = blockIdx.y * 128;
    const int bn = blockIdx.x * 128;
    const int tid = threadIdx.x;
    const int tr = tid >> 4, tc = tid & 15;
    const int lr = tid >> 1, lk = (tid & 1) * 4;

    const float* Ap = g_m + (size_t)(bm + lr) * GK + lk;
    const float* Bp = Wt  + (size_t)(bn + lr) * GK + lk;
    const float mu = g_stats[bm + lr][0];
    const float rs = g_stats[bm + lr][1];

    float acc[8][8];
    #pragma unroll
    for (int i = 0; i < 8; ++i)
        #pragma unroll
        for (int j = 0; j < 8; ++j) acc[i][j] = 0.f;

    float4 av = *(const float4*)(Ap);
    float4 bv = *(const float4*)(Bp);

    for (int k0 = 0; k0 < GK; k0 += 8) {
        float4 gv = *(const float4*)(lng + k0 + lk);
        float4 ov = *(const float4*)(lnb + k0 + lk);
        float4 an;
        an.x = (av.x - mu) * rs * gv.x + ov.x;
        an.y = (av.y - mu) * rs * gv.y + ov.y;
        an.z = (av.z - mu) * rs * gv.z + ov.z;
        an.w = (av.w - mu) * rs * gv.w + ov.w;
        __syncthreads();
        As[lk + 0][lr] = an.x; As[lk + 1][lr] = an.y;
        As[lk + 2][lr] = an.z; As[lk + 3][lr] = an.w;
        Bs[lk + 0][lr] = bv.x; Bs[lk + 1][lr] = bv.y;
        Bs[lk + 2][lr] = bv.z; Bs[lk + 3][lr] = bv.w;
        __syncthreads();
        if (k0 + 8 < GK) {
            av = *(const float4*)(Ap + k0 + 8);
            bv = *(const float4*)(Bp + k0 + 8);
        }
        #pragma unroll
        for (int kk = 0; kk < 8; ++kk) {
            float a[8], bb[8];
            #pragma unroll
            for (int i = 0; i < 8; ++i) a[i]  = As[kk][tr + 16 * i];
            #pragma unroll
            for (int j = 0; j < 8; ++j) bb[j] = Bs[kk][tc + 16 * j];
            #pragma unroll
            for (int i = 0; i < 8; ++i)
                #pragma unroll
                for (int j = 0; j < 8; ++j)
                    acc[i][j] = fmaf(a[i], bb[j], acc[i][j]);
        }
    }

    #pragma unroll
    for (int i = 0; i < 8; ++i) {
        int m = bm + tr + 16 * i;
        #pragma unroll
        for (int j = 0; j < 8; ++j) {
            int n = bn + tc + 16 * j;
            float d2 = fminf(fmaxf(acc[i][j] * 0.5f, -2.f), 2.f);
            C[(size_t)m * GN + n] = H[(size_t)m * GN + n] + d2;
        }
    }
}

// ---------------------------------------------------------------------
extern "C" void kernel_launch(void* const* d_in, const int* in_sizes, int n_in,
                              void* d_out, int out_size) {
    const float* h    = (const float*)d_in[0];
    const int*   mask = (const int*)  d_in[1];
    const float* lng  = (const float*)d_in[2];
    const float* lnb  = (const float*)d_in[3];
    const float* Wout = (const float*)d_in[4];
    const float* Wnm  = (const float*)d_in[5];
    const float* bnm  = (const float*)d_in[6];
    const float* Wwg  = (const float*)d_in[7];
    const float* bwg  = (const float*)d_in[8];
    float* out = (float*)d_out;

    cudaFuncSetAttribute(chunk_kernel,
                         cudaFuncAttributeMaxDynamicSharedMemorySize,
                         SMEM_BYTES);

    init_kernel<<<448, 256>>>();
    pre_kernel<<<Bq * NCq + Bq * (NCq - 1), 256>>>(h, Wnm, Wwg);

    for (int c = 0; c < NCq; ++c)
        chunk_kernel<<<72, 256, SMEM_BYTES>>>(h, mask, bnm, Wwg, bwg, c);

    mbuild_kernel<<<NCq * 56, 256>>>(h);
    stats_kernel<<<GM / 8, 256>>>();

    dim3 grid(GN / 128, GM / 128);
    gemm_kernel<<<grid, 256>>>(Wout, h, lng, lnb, out);
}

// round 6
// speedup vs baseline: 1.8776x; 1.8776x over previous
#include <cuda_runtime.h>
#include <math.h>

#define Bq 8
#define Tq 4096
#define Dq 896
#define Sq 64
#define Cq 128
#define NCq 32

#define GM (Bq*Tq)
#define GN Dq
#define GK Dq

// ---------------- global scratch ----------------
__device__ float g_G[Bq][NCq][Cq][Cq];        // self grams H_c H_c^T
__device__ float g_Gx[Bq][NCq][Cq][Cq];       // cross grams H_{c+1} H_c^T
__device__ float g_hd[Bq][Tq][4];             // h.Wnm_h, h.Wnm_m, h.Wwg_h, pad
__device__ float g_Ball[NCq][Bq][Sq][Dq];     // base memory at start of each chunk
__device__ float g_P[Bq][Cq][Sq];             // h_{c,t} . B_c[s]  (Q init)
__device__ float g_P0[Bq][Cq][Sq];            // h_{c+1,t} . B_c[s]
__device__ float g_u[Bq][Sq];                 // mem[s] . Wnm_m at chunk start
__device__ float g_beta[Bq][NCq][Cq][Sq];
__device__ float g_gamma[Bq][NCq][Cq][Cq];
__device__ float g_afinC[NCq][Bq][Sq];
__device__ float g_kapC[NCq][Bq][Cq];
__device__ int   g_idxC[NCq][Bq][Cq];
__device__ int   g_cnt[Bq];
__device__ float g_m[(size_t)Bq*Tq*Dq];
__device__ float g_stats[(size_t)Bq*Tq][2];

// smem layout (float offsets) for chunk_kernel scan blocks
#define OF_Q    0                  // 128*65 = 8320
#define OF_GX   8320               // 128*128 = 16384
#define OF_HD   24704              // 512 (float4[128])
#define OF_ESM  25216              // 64
#define OF_A    25280              // 64
#define OF_R    25344              // rS [128]
#define OF_IDX  25472              // idxS [128] (int)
#define OF_KF   25600              // kapF [128]
#define OF_MSK  25728              // 256 (uint 64x4)
#define SMEM_FLOATS 25984
#define SMEM_BYTES (SMEM_FLOATS*4)

__device__ __forceinline__ unsigned okey(float f) {
    unsigned u = __float_as_uint(f);
    return (u & 0x80000000u) ? ~u : (u | 0x80000000u);
}
__device__ __forceinline__ float dekey(unsigned k) {
    unsigned u = (k & 0x80000000u) ? (k ^ 0x80000000u) : ~k;
    return __uint_as_float(u);
}

// ---------------------------------------------------------------------
__global__ void init_kernel() {
    int tid = blockIdx.x * blockDim.x + threadIdx.x;
    int stride = gridDim.x * blockDim.x;
    int nb = Bq * Sq * Dq;
    for (int i = tid; i < nb; i += stride) (&g_Ball[0][0][0][0])[i] = 0.f;
    int np = Bq * Cq * Sq;
    for (int i = tid; i < np; i += stride) {
        (&g_P[0][0][0])[i] = 0.f;
        (&g_P0[0][0][0])[i] = 0.f;
    }
    if (tid < Bq * Sq) (&g_u[0][0])[tid] = 0.f;
    if (tid < Bq) g_cnt[tid] = 0;
}

// ---------------------------------------------------------------------
// pre: blocks [0,256): G[b][c] = Hc Hc^T (+ h-dot vectors)
//      blocks [256,504): Gx[b][c] = H_{c+1} Hc^T
// ---------------------------------------------------------------------
__global__ __launch_bounds__(256) void pre_kernel(
    const float* __restrict__ h,
    const float* __restrict__ W_nm,
    const float* __restrict__ W_wg)
{
    __shared__ float As[8][128];
    __shared__ float Bs[8][128];

    const int tid = threadIdx.x;
    const int tr = tid >> 4, tc = tid & 15;
    const int lr = tid >> 1, lk = (tid & 1) * 4;

    int b, c;
    const float *Arow, *Brow;
    float* outp;
    bool doHd;
    if (blockIdx.x < Bq * NCq) {
        b = blockIdx.x / NCq; c = blockIdx.x % NCq;
        Arow = h + ((size_t)b * Tq + c * Cq) * Dq;
        Brow = Arow;
        outp = &g_G[b][c][0][0];
        doHd = true;
    } else {
        int k = blockIdx.x - Bq * NCq;
        b = k / (NCq - 1); c = k % (NCq - 1);
        Arow = h + ((size_t)b * Tq + (c + 1) * Cq) * Dq;
        Brow = h + ((size_t)b * Tq + c * Cq) * Dq;
        outp = &g_Gx[b][c][0][0];
        doHd = false;
    }

    float acc[8][8];
    #pragma unroll
    for (int i = 0; i < 8; ++i)
        #pragma unroll
        for (int j = 0; j < 8; ++j) acc[i][j] = 0.f;

    float4 av = *(const float4*)(Arow + (size_t)lr * Dq + lk);
    float4 bv = *(const float4*)(Brow + (size_t)lr * Dq + lk);
    for (int k0 = 0; k0 < Dq; k0 += 8) {
        __syncthreads();
        As[lk + 0][lr] = av.x; As[lk + 1][lr] = av.y;
        As[lk + 2][lr] = av.z; As[lk + 3][lr] = av.w;
        Bs[lk + 0][lr] = bv.x; Bs[lk + 1][lr] = bv.y;
        Bs[lk + 2][lr] = bv.z; Bs[lk + 3][lr] = bv.w;
        __syncthreads();
        if (k0 + 8 < Dq) {
            av = *(const float4*)(Arow + (size_t)lr * Dq + k0 + 8 + lk);
            bv = *(const float4*)(Brow + (size_t)lr * Dq + k0 + 8 + lk);
        }
        #pragma unroll
        for (int kk = 0; kk < 8; ++kk) {
            float a[8], bb[8];
            #pragma unroll
            for (int i = 0; i < 8; ++i) a[i]  = As[kk][tr + 16 * i];
            #pragma unroll
            for (int j = 0; j < 8; ++j) bb[j] = Bs[kk][tc + 16 * j];
            #pragma unroll
            for (int i = 0; i < 8; ++i)
                #pragma unroll
                for (int j = 0; j < 8; ++j)
                    acc[i][j] = fmaf(a[i], bb[j], acc[i][j]);
        }
    }
    #pragma unroll
    for (int i = 0; i < 8; ++i)
        #pragma unroll
        for (int j = 0; j < 8; ++j)
            outp[(tr + 16 * i) * Cq + tc + 16 * j] = acc[i][j];

    if (doHd) {
        const int w = tid >> 5, l = tid & 31;
        const int t0 = c * Cq;
        for (int r = w; r < Cq; r += 8) {
            const float* hr = Arow + (size_t)r * Dq;
            float s0 = 0.f, s1 = 0.f, s2 = 0.f;
            for (int d = l; d < Dq; d += 32) {
                float x = hr[d];
                s0 += x * W_nm[d];
                s1 += x * W_nm[Dq + d];
                s2 += x * W_wg[d];
            }
            #pragma unroll
            for (int o = 16; o > 0; o >>= 1) {
                s0 += __shfl_xor_sync(0xffffffffu, s0, o);
                s1 += __shfl_xor_sync(0xffffffffu, s1, o);
                s2 += __shfl_xor_sync(0xffffffffu, s2, o);
            }
            if (l == 0) {
                g_hd[b][t0 + r][0] = s0;
                g_hd[b][t0 + r][1] = s1;
                g_hd[b][t0 + r][2] = s2;
                g_hd[b][t0 + r][3] = 0.f;
            }
        }
    }
}

// ---------------------------------------------------------------------
// chunk launch c:
//   blocks 0..7  : scan(c) with incremental Q matrix; warps 1-7 stage Gx;
//                  then spin on B-path and fixup -> g_P (Q init for c+1)
//   blocks 8..71 : build B_c from scan(c-1), P0 = H_{c+1}.B_c, bump counter
// ---------------------------------------------------------------------
__global__ __launch_bounds__(256) void chunk_kernel(
    const float* __restrict__ h, const int* __restrict__ mask,
    const float* __restrict__ b_nm, const float* __restrict__ W_wg,
    const float* __restrict__ b_wg, int c)
{
    extern __shared__ float sm[];
    const int tid = threadIdx.x;

    if (blockIdx.x < 8) {
        float*    Qs   = sm + OF_Q;     // [128][65]
        float*    sGx  = sm + OF_GX;
        float4*   sHd  = (float4*)(sm + OF_HD);
        float*    esm  = sm + OF_ESM;
        float*    Asm  = sm + OF_A;
        float*    rS   = sm + OF_R;
        int*      idxS = (int*)(sm + OF_IDX);
        float*    kapF = sm + OF_KF;
        unsigned* mskS = (unsigned*)(sm + OF_MSK);

        const int b = blockIdx.x;
        const int t0 = c * Cq;

        // stage Q (= P), hd, init bookkeeping
        for (int i = tid; i < Cq * Sq; i += 256) {
            int tau = i >> 6, s = i & 63;
            Qs[tau * 65 + s] = g_P[b][tau][s];
        }
        if (tid < Cq) {
            float4 hv = ((const float4*)g_hd)[(size_t)b * Tq + t0 + tid];
            hv.w = (float)mask[b * Tq + t0 + tid];
            sHd[tid] = hv;
        }
        if (tid < Sq) Asm[tid] = 1.f;
        if (tid < Cq) { rS[tid] = 0.f; idxS[tid] = 0; }
        mskS[tid] = 0;   // 256 words
        __syncthreads();

        if (tid < 32) {
            // ---------------- scan (warp 0) ----------------
            const int l = tid;
            const float scale = rsqrtf((float)Dq);
            const float wwgg = W_wg[Dq];
            const float bnm = b_nm[0], bwg = b_wg[0];
            float A0 = 1.f, A1 = 1.f;
            float R0 = g_u[b][l], R1 = g_u[b][l + 32];
            const float* Gp = &g_G[b][c][0][0];
            float* bet = &g_beta[b][c][0][0];
            float* gam = &g_gamma[b][c][0][0];

            float gc0 = __ldg(Gp + l),      gc1 = __ldg(Gp + l + 32);
            float gc2 = __ldg(Gp + l + 64), gc3 = __ldg(Gp + l + 96);

            for (int t = 0; t < Cq; ++t) {
                float gn0, gn1, gn2, gn3;
                if (t + 1 < Cq) {
                    const float* gr = Gp + (t + 1) * Cq;
                    gn0 = __ldg(gr + l);      gn1 = __ldg(gr + l + 32);
                    gn2 = __ldg(gr + l + 64); gn3 = __ldg(gr + l + 96);
                }

                float s0 = Qs[t * 65 + l] * scale;
                float s1 = Qs[t * 65 + l + 32] * scale;

                unsigned k0 = okey(s0), k1 = okey(s1);
                unsigned kmx = __reduce_max_sync(0xffffffffu, k0 > k1 ? k0 : k1);
                float mx = dekey(kmx);
                unsigned cand = (k0 == kmx) ? (unsigned)l
                              : (k1 == kmx) ? (unsigned)(l + 32) : 1000u;
                int mi = (int)__reduce_min_sync(0xffffffffu, cand);

                float e0 = __expf(s0 - mx), e1 = __expf(s1 - mx);
                esm[l] = e0; esm[l + 32] = e1;

                float pe = e0 + e1;
                float pd = e0 * R0 + e1 * R1;
                #pragma unroll
                for (int o = 16; o > 0; o >>= 1) {
                    pe += __shfl_xor_sync(0xffffffffu, pe, o);
                    pd += __shfl_xor_sync(0xffffffffu, pd, o);
                }
                float inv = 1.f / pe;
                float mdot = pd * inv;

                float4 hdt = sHd[t];
                float gg = 1.f / (1.f + __expf(-(hdt.x + mdot + bnm)));
                float wg = 1.f / (1.f + __expf(-(hdt.z + gg * wwgg + bwg)));
                wg = fminf(wg, 0.2f) * hdt.w;

                __syncwarp();   // esm visible; pre-update state readable

                // emit beta / gamma (pre-update coefficients)
                bet[t * Sq + l]      = e0 * inv * A0;
                bet[t * Sq + l + 32] = e1 * inv * A1;
                #pragma unroll
                for (int q = 0; q < 4; ++q) {
                    int j = l + 32 * q;
                    float gv = 0.f;
                    if (j < t) {
                        int ix = idxS[j];
                        gv = esm[ix] * inv * (rS[j] * Asm[ix]);
                    }
                    gam[t * Cq + j] = gv;
                }
                __syncwarp();   // gamma reads done before state update

                // apply write
                float dec = 1.f - wg;
                if (mi == l) {
                    A0 *= dec;
                    R0 = fmaf(dec, R0, wg * hdt.y);
                    Asm[mi] = A0;
                    rS[t] = wg / A0;
                    idxS[t] = mi;
                    mskS[mi * 4 + (t >> 5)] |= 1u << (t & 31);
                } else if (mi == l + 32) {
                    A1 *= dec;
                    R1 = fmaf(dec, R1, wg * hdt.y);
                    Asm[mi] = A1;
                    rS[t] = wg / A1;
                    idxS[t] = mi;
                    mskS[mi * 4 + (t >> 5)] |= 1u << (t & 31);
                }
                // Q column update (all future rows)
                {
                    float v;
                    v = Qs[l * 65 + mi];
                    Qs[l * 65 + mi] = fmaf(dec, v, wg * gc0);
                    v = Qs[(l + 32) * 65 + mi];
                    Qs[(l + 32) * 65 + mi] = fmaf(dec, v, wg * gc1);
                    v = Qs[(l + 64) * 65 + mi];
                    Qs[(l + 64) * 65 + mi] = fmaf(dec, v, wg * gc2);
                    v = Qs[(l + 96) * 65 + mi];
                    Qs[(l + 96) * 65 + mi] = fmaf(dec, v, wg * gc3);
                }
                __syncwarp();   // updates visible next step
                gc0 = gn0; gc1 = gn1; gc2 = gn2; gc3 = gn3;
            }

            // epilogue: final coefficients + state for B path / fixup
            g_u[b][l] = R0; g_u[b][l + 32] = R1;
            g_afinC[c][b][l] = A0; g_afinC[c][b][l + 32] = A1;
            #pragma unroll
            for (int q = 0; q < 4; ++q) {
                int j = l + 32 * q;
                int ix = idxS[j];
                float kv = rS[j] * Asm[ix];
                kapF[j] = kv;
                g_kapC[c][b][j] = kv;
                g_idxC[c][b][j] = ix;
            }
        } else if (c < NCq - 1) {
            // warps 1-7: stage Gx during scan
            const float4* xsrc = (const float4*)&g_Gx[b][c][0][0];
            for (int i = tid - 32; i < Cq * Cq / 4; i += 224)
                ((float4*)sGx)[i] = xsrc[i];
        }
        __syncthreads();

        if (c < NCq - 1) {
            if (tid == 0) {
                volatile int* vc = (volatile int*)&g_cnt[0];
                while (vc[b] < 8 * (c + 1)) {}
                __threadfence();
            }
            __syncthreads();
            // fixup: g_P[t][s] = af_s * P0[t][s] + sum_{j in slot s} kap_j * Gx[t][j]
            const int tau = tid >> 1, base = (tid & 1) * 32;
            const float* P0r = &g_P0[b][tau][0];
            const float* gxr = sGx + tau * Cq;
            float* Pr = &g_P[b][tau][0];
            for (int q = 0; q < 32; ++q) {
                int s = base + q;
                float v = Asm[s] * P0r[s];
                #pragma unroll
                for (int w2 = 0; w2 < 4; ++w2) {
                    unsigned wd = mskS[s * 4 + w2];
                    while (wd) {
                        int bp = __ffs(wd) - 1; wd &= wd - 1;
                        int j = w2 * 32 + bp;
                        v = fmaf(kapF[j], gxr[j], v);
                    }
                }
                Pr[s] = v;
            }
        }
    } else {
        // -------- B path: build B_c from scan(c-1), then P0 = H_{c+1}.B_c --------
        const int id = blockIdx.x - 8;
        const int b = id >> 3, s0 = (id & 7) * 8;

        if (c == 0) {
            if (tid == 0) { __threadfence(); atomicAdd(&g_cnt[b], 1); }
            return;
        }

        float* kap2 = sm;
        int*   idx2 = (int*)(sm + 128);
        float* af2  = sm + 256;
        if (tid < Cq) { kap2[tid] = g_kapC[c - 1][b][tid]; idx2[tid] = g_idxC[c - 1][b][tid]; }
        if (tid < 8)  af2[tid] = g_afinC[c - 1][b][s0 + tid];
        __syncthreads();

        const int w = tid >> 5, l = tid & 31;
        const float* Hp = h + ((size_t)b * Tq + (c - 1) * Cq) * Dq;
        {
            const int s = s0 + w;
            const float4* Bo = (const float4*)&g_Ball[c - 1][b][s][0];
            float4*       Bn = (float4*)&g_Ball[c][b][s][0];
            const float as = af2[w];
            float4 acc[7];
            #pragma unroll
            for (int q = 0; q < 7; ++q) {
                float4 v = Bo[q * 32 + l];
                acc[q] = make_float4(as * v.x, as * v.y, as * v.z, as * v.w);
            }
            for (int j = 0; j < Cq; ++j) {
                if (idx2[j] == s) {
                    float kj = kap2[j];
                    const float4* hjp = (const float4*)(Hp + (size_t)j * Dq);
                    #pragma unroll
                    for (int q = 0; q < 7; ++q) {
                        float4 hv = hjp[q * 32 + l];
                        acc[q].x += kj * hv.x; acc[q].y += kj * hv.y;
                        acc[q].z += kj * hv.z; acc[q].w += kj * hv.w;
                    }
                }
            }
            #pragma unroll
            for (int q = 0; q < 7; ++q) Bn[q * 32 + l] = acc[q];
        }
        __syncthreads();

        if (c < NCq - 1) {
            const int t = tid >> 1, sh = (tid & 1) * 4;
            const float4* Hn = (const float4*)(h + ((size_t)b * Tq + (c + 1) * Cq + t) * Dq);
            const float4* B0 = (const float4*)&g_Ball[c][b][s0 + sh + 0][0];
            const float4* B1 = (const float4*)&g_Ball[c][b][s0 + sh + 1][0];
            const float4* B2 = (const float4*)&g_Ball[c][b][s0 + sh + 2][0];
            const float4* B3 = (const float4*)&g_Ball[c][b][s0 + sh + 3][0];
            float a0 = 0.f, a1 = 0.f, a2 = 0.f, a3 = 0.f;
            #pragma unroll 4
            for (int k = 0; k < Dq / 4; ++k) {
                float4 hv = Hn[k];
                float4 x;
                x = B0[k]; a0 += hv.x * x.x + hv.y * x.y + hv.z * x.z + hv.w * x.w;
                x = B1[k]; a1 += hv.x * x.x + hv.y * x.y + hv.z * x.z + hv.w * x.w;
                x = B2[k]; a2 += hv.x * x.x + hv.y * x.y + hv.z * x.z + hv.w * x.w;
                x = B3[k]; a3 += hv.x * x.x + hv.y * x.y + hv.z * x.z + hv.w * x.w;
            }
            g_P0[b][t][s0 + sh + 0] = a0;
            g_P0[b][t][s0 + sh + 1] = a1;
            g_P0[b][t][s0 + sh + 2] = a2;
            g_P0[b][t][s0 + sh + 3] = a3;
            __syncthreads();
            if (tid == 0) { __threadfence(); atomicAdd(&g_cnt[b], 1); }
        }
    }
}

// ---------------------------------------------------------------------
// m-build over ALL chunks: m = [beta|gamma] @ [B_c ; H_c]
// ---------------------------------------------------------------------
__global__ __launch_bounds__(256) void mbuild_kernel(const float* __restrict__ h)
{
    __shared__ float As2[8][128];
    __shared__ float Bs[8][128];

    const int cc = blockIdx.x / 56;
    const int r  = blockIdx.x % 56;
    const int b  = r / 7;
    const int n0 = (r % 7) * 128;
    const int t0 = cc * Cq;
    const int tid = threadIdx.x;

    const float* Bold = &g_Ball[cc][b][0][0];
    const float* Hc = h + ((size_t)b * Tq + t0) * Dq;
    const float* bet = &g_beta[b][cc][0][0];
    const float* gam = &g_gamma[b][cc][0][0];

    const int tr = tid >> 4, tc = tid & 15;
    const int lr = tid >> 1, lk = (tid & 1) * 4;
    const int kr = tid >> 5, nc = (tid & 31) * 4;

    float acc[8][8];
    #pragma unroll
    for (int i = 0; i < 8; ++i)
        #pragma unroll
        for (int j = 0; j < 8; ++j) acc[i][j] = 0.f;

    for (int k0 = 0; k0 < Sq + Cq; k0 += 8) {
        float4 av = (k0 < Sq)
            ? *(const float4*)(bet + lr * Sq + k0 + lk)
            : *(const float4*)(gam + lr * Cq + k0 - Sq + lk);
        int kg = k0 + kr;
        const float* rp = (kg < Sq) ? (Bold + (size_t)kg * Dq)
                                    : (Hc + (size_t)(kg - Sq) * Dq);
        float4 bv = *(const float4*)(rp + n0 + nc);
        __syncthreads();
        As2[lk + 0][lr] = av.x; As2[lk + 1][lr] = av.y;
        As2[lk + 2][lr] = av.z; As2[lk + 3][lr] = av.w;
        Bs[kr][nc + 0] = bv.x; Bs[kr][nc + 1] = bv.y;
        Bs[kr][nc + 2] = bv.z; Bs[kr][nc + 3] = bv.w;
        __syncthreads();
        #pragma unroll
        for (int kk = 0; kk < 8; ++kk) {
            float a[8], bb[8];
            #pragma unroll
            for (int i = 0; i < 8; ++i) a[i]  = As2[kk][tr + 16 * i];
            #pragma unroll
            for (int j = 0; j < 8; ++j) bb[j] = Bs[kk][tc + 16 * j];
            #pragma unroll
            for (int i = 0; i < 8; ++i)
                #pragma unroll
                for (int j = 0; j < 8; ++j)
                    acc[i][j] = fmaf(a[i], bb[j], acc[i][j]);
        }
    }
    #pragma unroll
    for (int i = 0; i < 8; ++i) {
        size_t row = (size_t)b * Tq + t0 + tr + 16 * i;
        #pragma unroll
        for (int j = 0; j < 8; ++j)
            g_m[row * Dq + n0 + tc + 16 * j] = acc[i][j];
    }
}

// ---------------------------------------------------------------------
__global__ __launch_bounds__(256) void stats_kernel() {
    int row = blockIdx.x * 8 + (threadIdx.x >> 5);
    int l = threadIdx.x & 31;
    const float* mr = g_m + (size_t)row * Dq;
    float s = 0.f, s2 = 0.f;
    for (int d = l; d < Dq; d += 32) { float v = mr[d]; s += v; s2 += v * v; }
    #pragma unroll
    for (int o = 16; o > 0; o >>= 1) {
        s  += __shfl_xor_sync(0xffffffffu, s, o);
        s2 += __shfl_xor_sync(0xffffffffu, s2, o);
    }
    if (l == 0) {
        float mu = s * (1.f / (float)Dq);
        float var = s2 * (1.f / (float)Dq) - mu * mu;
        g_stats[row][0] = mu;
        g_stats[row][1] = rsqrtf(var + 1e-5f);
    }
}

// ---------------------------------------------------------------------
__global__ __launch_bounds__(256) void gemm_kernel(
    const float* __restrict__ Wt,
    const float* __restrict__ H,
    const float* __restrict__ lng,
    const float* __restrict__ lnb,
    float* __restrict__ C)
{
    __shared__ float As[8][128];
    __shared__ float Bs[8][128];

    const int bm = blockIdx.y * 128;
    const int bn = blockIdx.x * 128;
    const int tid = threadIdx.x;
    const int tr = tid >> 4, tc = tid & 15;
    const int lr = tid >> 1, lk = (tid & 1) * 4;

    const float* Ap = g_m + (size_t)(bm + lr) * GK + lk;
    const float* Bp = Wt  + (size_t)(bn + lr) * GK + lk;
    const float mu = g_stats[bm + lr][0];
    const float rs = g_stats[bm + lr][1];

    float acc[8][8];
    #pragma unroll
    for (int i = 0; i < 8; ++i)
        #pragma unroll
        for (int j = 0; j < 8; ++j) acc[i][j] = 0.f;

    float4 av = *(const float4*)(Ap);
    float4 bv = *(const float4*)(Bp);

    for (int k0 = 0; k0 < GK; k0 += 8) {
        float4 gv = *(const float4*)(lng + k0 + lk);
        float4 ov = *(const float4*)(lnb + k0 + lk);
        float4 an;
        an.x = (av.x - mu) * rs * gv.x + ov.x;
        an.y = (av.y - mu) * rs * gv.y + ov.y;
        an.z = (av.z - mu) * rs * gv.z + ov.z;
        an.w = (av.w - mu) * rs * gv.w + ov.w;
        __syncthreads();
        As[lk + 0][lr] = an.x; As[lk + 1][lr] = an.y;
        As[lk + 2][lr] = an.z; As[lk + 3][lr] = an.w;
        Bs[lk + 0][lr] = bv.x; Bs[lk + 1][lr] = bv.y;
        Bs[lk + 2][lr] = bv.z; Bs[lk + 3][lr] = bv.w;
        __syncthreads();
        if (k0 + 8 < GK) {
            av = *(const float4*)(Ap + k0 + 8);
            bv = *(const float4*)(Bp + k0 + 8);
        }
        #pragma unroll
        for (int kk = 0; kk < 8; ++kk) {
            float a[8], bb[8];
            #pragma unroll
            for (int i = 0; i < 8; ++i) a[i]  = As[kk][tr + 16 * i];
            #pragma unroll
            for (int j = 0; j < 8; ++j) bb[j] = Bs[kk][tc + 16 * j];
            #pragma unroll
            for (int i = 0; i < 8; ++i)
                #pragma unroll
                for (int j = 0; j < 8; ++j)
                    acc[i][j] = fmaf(a[i], bb[j], acc[i][j]);
        }
    }

    #pragma unroll
    for (int i = 0; i < 8; ++i) {
        int m = bm + tr + 16 * i;
        #pragma unroll
        for (int j = 0; j < 8; ++j) {
            int n = bn + tc + 16 * j;
            float d2 = fminf(fmaxf(acc[i][j] * 0.5f, -2.f), 2.f);
            C[(size_t)m * GN + n] = H[(size_t)m * GN + n] + d2;
        }
    }
}

// ---------------------------------------------------------------------
extern "C" void kernel_launch(void* const* d_in, const int* in_sizes, int n_in,
                              void* d_out, int out_size) {
    const float* h    = (const float*)d_in[0];
    const int*   mask = (const int*)  d_in[1];
    const float* lng  = (const float*)d_in[2];
    const float* lnb  = (const float*)d_in[3];
    const float* Wout = (const float*)d_in[4];
    const float* Wnm  = (const float*)d_in[5];
    const float* bnm  = (const float*)d_in[6];
    const float* Wwg  = (const float*)d_in[7];
    const float* bwg  = (const float*)d_in[8];
    float* out = (float*)d_out;

    cudaFuncSetAttribute(chunk_kernel,
                         cudaFuncAttributeMaxDynamicSharedMemorySize,
                         SMEM_BYTES);

    init_kernel<<<448, 256>>>();
    pre_kernel<<<Bq * NCq + Bq * (NCq - 1), 256>>>(h, Wnm, Wwg);

    for (int c = 0; c < NCq; ++c)
        chunk_kernel<<<72, 256, SMEM_BYTES>>>(h, mask, bnm, Wwg, bwg, c);

    mbuild_kernel<<<NCq * 56, 256>>>(h);
    stats_kernel<<<GM / 8, 256>>>();

    dim3 grid(GN / 128, GM / 128);
    gemm_kernel<<<grid, 256>>>(Wout, h, lng, lnb, out);
}

// round 7
// speedup vs baseline: 2.0110x; 1.0710x over previous
#include <cuda_runtime.h>
#include <math.h>

#define Bq 8
#define Tq 4096
#define Dq 896
#define Sq 64
#define Cq 128
#define NCq 32

#define GM (Bq*Tq)
#define GN Dq
#define GK Dq

// ---------------- global scratch ----------------
__device__ float g_G[Bq][NCq][Cq][Cq];        // self grams H_c H_c^T
__device__ float g_Gx[Bq][NCq][Cq][Cq];       // cross grams H_{c+1} H_c^T
__device__ float g_hd[Bq][Tq][4];             // h.Wnm_h, h.Wnm_m, h.Wwg_h, pad
__device__ float g_Ball[NCq][Bq][Sq][Dq];     // base memory at start of each chunk
__device__ float g_P0[Bq][Cq][Sq];            // h_{c+1,t} . B_c[s]
__device__ float g_u[Bq][Sq];                 // mem[s] . Wnm_m at chunk start
__device__ float g_beta[Bq][NCq][Cq][Sq];
__device__ float g_gamma[Bq][NCq][Cq][Cq];
__device__ float g_afinC[NCq][Bq][Sq];
__device__ float g_kapC[NCq][Bq][Cq];
__device__ int   g_idxC[NCq][Bq][Cq];
__device__ unsigned g_mskC[NCq][Bq][Sq][4];
__device__ float g_m[(size_t)Bq*Tq*Dq];
__device__ float g_stats[(size_t)Bq*Tq][2];

// smem layout (float offsets) for chunk_kernel scan blocks
#define OF_Q    0                  // 128*65 = 8320
#define OF_GX   8320               // 128*128 = 16384
#define OF_HD   24704              // 512 (float4[128])
#define OF_ESM  25216              // 64
#define OF_A    25280              // 64
#define OF_R    25344              // 128
#define OF_IDX  25472              // 128 (int)
#define OF_MSK  25600              // 256 (uint 64x4)
#define OF_KF   25856              // 128 (fixup kappa staging)
#define SMEM_FLOATS 25984
#define SMEM_BYTES (SMEM_FLOATS*4)

__device__ __forceinline__ unsigned okey(float f) {
    unsigned u = __float_as_uint(f);
    return (u & 0x80000000u) ? ~u : (u | 0x80000000u);
}
__device__ __forceinline__ float dekey(unsigned k) {
    unsigned u = (k & 0x80000000u) ? (k ^ 0x80000000u) : ~k;
    return __uint_as_float(u);
}

// ---------------------------------------------------------------------
__global__ void init_kernel() {
    int tid = blockIdx.x * blockDim.x + threadIdx.x;
    int stride = gridDim.x * blockDim.x;
    int nb = Bq * Sq * Dq;
    for (int i = tid; i < nb; i += stride) (&g_Ball[0][0][0][0])[i] = 0.f;
    int np = Bq * Cq * Sq;
    for (int i = tid; i < np; i += stride) (&g_P0[0][0][0])[i] = 0.f;
    if (tid < Bq * Sq) (&g_u[0][0])[tid] = 0.f;
}

// ---------------------------------------------------------------------
// pre: blocks [0,256): G[b][c] = Hc Hc^T (+ h-dot vectors)
//      blocks [256,504): Gx[b][c] = H_{c+1} Hc^T
// ---------------------------------------------------------------------
__global__ __launch_bounds__(256) void pre_kernel(
    const float* __restrict__ h,
    const float* __restrict__ W_nm,
    const float* __restrict__ W_wg)
{
    __shared__ float As[8][128];
    __shared__ float Bs[8][128];

    const int tid = threadIdx.x;
    const int tr = tid >> 4, tc = tid & 15;
    const int lr = tid >> 1, lk = (tid & 1) * 4;

    int b, c;
    const float *Arow, *Brow;
    float* outp;
    bool doHd;
    if (blockIdx.x < Bq * NCq) {
        b = blockIdx.x / NCq; c = blockIdx.x % NCq;
        Arow = h + ((size_t)b * Tq + c * Cq) * Dq;
        Brow = Arow;
        outp = &g_G[b][c][0][0];
        doHd = true;
    } else {
        int k = blockIdx.x - Bq * NCq;
        b = k / (NCq - 1); c = k % (NCq - 1);
        Arow = h + ((size_t)b * Tq + (c + 1) * Cq) * Dq;
        Brow = h + ((size_t)b * Tq + c * Cq) * Dq;
        outp = &g_Gx[b][c][0][0];
        doHd = false;
    }

    float acc[8][8];
    #pragma unroll
    for (int i = 0; i < 8; ++i)
        #pragma unroll
        for (int j = 0; j < 8; ++j) acc[i][j] = 0.f;

    float4 av = *(const float4*)(Arow + (size_t)lr * Dq + lk);
    float4 bv = *(const float4*)(Brow + (size_t)lr * Dq + lk);
    for (int k0 = 0; k0 < Dq; k0 += 8) {
        __syncthreads();
        As[lk + 0][lr] = av.x; As[lk + 1][lr] = av.y;
        As[lk + 2][lr] = av.z; As[lk + 3][lr] = av.w;
        Bs[lk + 0][lr] = bv.x; Bs[lk + 1][lr] = bv.y;
        Bs[lk + 2][lr] = bv.z; Bs[lk + 3][lr] = bv.w;
        __syncthreads();
        if (k0 + 8 < Dq) {
            av = *(const float4*)(Arow + (size_t)lr * Dq + k0 + 8 + lk);
            bv = *(const float4*)(Brow + (size_t)lr * Dq + k0 + 8 + lk);
        }
        #pragma unroll
        for (int kk = 0; kk < 8; ++kk) {
            float a[8], bb[8];
            #pragma unroll
            for (int i = 0; i < 8; ++i) a[i]  = As[kk][tr + 16 * i];
            #pragma unroll
            for (int j = 0; j < 8; ++j) bb[j] = Bs[kk][tc + 16 * j];
            #pragma unroll
            for (int i = 0; i < 8; ++i)
                #pragma unroll
                for (int j = 0; j < 8; ++j)
                    acc[i][j] = fmaf(a[i], bb[j], acc[i][j]);
        }
    }
    #pragma unroll
    for (int i = 0; i < 8; ++i)
        #pragma unroll
        for (int j = 0; j < 8; ++j)
            outp[(tr + 16 * i) * Cq + tc + 16 * j] = acc[i][j];

    if (doHd) {
        const int w = tid >> 5, l = tid & 31;
        const int t0 = c * Cq;
        for (int r = w; r < Cq; r += 8) {
            const float* hr = Arow + (size_t)r * Dq;
            float s0 = 0.f, s1 = 0.f, s2 = 0.f;
            for (int d = l; d < Dq; d += 32) {
                float x = hr[d];
                s0 += x * W_nm[d];
                s1 += x * W_nm[Dq + d];
                s2 += x * W_wg[d];
            }
            #pragma unroll
            for (int o = 16; o > 0; o >>= 1) {
                s0 += __shfl_xor_sync(0xffffffffu, s0, o);
                s1 += __shfl_xor_sync(0xffffffffu, s1, o);
                s2 += __shfl_xor_sync(0xffffffffu, s2, o);
            }
            if (l == 0) {
                g_hd[b][t0 + r][0] = s0;
                g_hd[b][t0 + r][1] = s1;
                g_hd[b][t0 + r][2] = s2;
                g_hd[b][t0 + r][3] = 0.f;
            }
        }
    }
}

// ---------------------------------------------------------------------
// chunk launch c (NO intra-launch dependencies; launch boundary orders all):
//   blocks 0..7    : fixup(Q from P0(c-1)+Gx[c-1]+writes(c-1)) then scan(c)
//   blocks 8..135  : build B_c from scan(c-1); P0(c) = H_{c+1}.B_c
// ---------------------------------------------------------------------
__global__ __launch_bounds__(256) void chunk_kernel(
    const float* __restrict__ h, const int* __restrict__ mask,
    const float* __restrict__ b_nm, const float* __restrict__ W_wg,
    const float* __restrict__ b_wg, int c)
{
    extern __shared__ float sm[];
    const int tid = threadIdx.x;

    if (blockIdx.x < 8) {
        float*    Qs   = sm + OF_Q;     // [128][65]
        float*    sGx  = sm + OF_GX;    // [128][128]
        float4*   sHd  = (float4*)(sm + OF_HD);
        float*    esm  = sm + OF_ESM;
        float*    Asm  = sm + OF_A;
        float*    rS   = sm + OF_R;
        int*      idxS = (int*)(sm + OF_IDX);
        unsigned* mskS = (unsigned*)(sm + OF_MSK);
        float*    kapF = sm + OF_KF;

        const int b = blockIdx.x;
        const int t0 = c * Cq;

        // ---- stage ----
        if (tid < Cq) {
            float4 hv = ((const float4*)g_hd)[(size_t)b * Tq + t0 + tid];
            hv.w = (float)mask[b * Tq + t0 + tid];
            sHd[tid] = hv;
        }
        if (c > 0) {
            const float4* xsrc = (const float4*)&g_Gx[b][c - 1][0][0];
            #pragma unroll 4
            for (int i = tid; i < Cq * Cq / 4; i += 256)
                ((float4*)sGx)[i] = xsrc[i];
            if (tid < Sq) Asm[tid] = g_afinC[c - 1][b][tid];
            if (tid < Cq) {
                kapF[tid] = g_kapC[c - 1][b][tid];
                idxS[tid] = g_idxC[c - 1][b][tid];
            }
        }
        __syncthreads();

        // ---- fixup: Q(c) = af*P0(c-1) + sum_j kap_j * Gx[c-1] ----
        if (c == 0) {
            for (int i = tid; i < Cq * Sq; i += 256) {
                int tau = i >> 6, s = i & 63;
                Qs[tau * 65 + s] = 0.f;
            }
        } else {
            const int t = tid >> 1, hf = (tid & 1) * 32;
            const float* P0r = &g_P0[b][t][0];
            float* Qr = Qs + t * 65;
            #pragma unroll 8
            for (int q = 0; q < 32; ++q) {
                int s = hf + q;
                Qr[s] = Asm[s] * P0r[s];
            }
            const float* gxr = sGx + t * Cq;
            for (int j = 0; j < Cq; ++j) {
                int s = idxS[j];
                if ((unsigned)(s - hf) < 32u)
                    Qr[s] = fmaf(kapF[j], gxr[j], Qr[s]);
            }
        }
        __syncthreads();
        // reinit scan bookkeeping
        if (tid < Sq) Asm[tid] = 1.f;
        if (tid < Cq) { rS[tid] = 0.f; idxS[tid] = 0; }
        mskS[tid] = 0;
        __syncthreads();

        if (tid < 32) {
            // ---------------- scan (warp 0) ----------------
            const int l = tid;
            const float scale = rsqrtf((float)Dq);
            const float wwgg = W_wg[Dq];
            const float bnm = b_nm[0], bwg = b_wg[0];
            float A0 = 1.f, A1 = 1.f;
            float R0 = g_u[b][l], R1 = g_u[b][l + 32];
            const float* Gp = &g_G[b][c][0][0];
            float* bet = &g_beta[b][c][0][0];
            float* gam = &g_gamma[b][c][0][0];

            float gc0 = __ldg(Gp + l),      gc1 = __ldg(Gp + l + 32);
            float gc2 = __ldg(Gp + l + 64), gc3 = __ldg(Gp + l + 96);

            for (int t = 0; t < Cq; ++t) {
                float gn0, gn1, gn2, gn3;
                if (t + 1 < Cq) {
                    const float* gr = Gp + (t + 1) * Cq;
                    gn0 = __ldg(gr + l);      gn1 = __ldg(gr + l + 32);
                    gn2 = __ldg(gr + l + 64); gn3 = __ldg(gr + l + 96);
                }

                float s0 = Qs[t * 65 + l] * scale;
                float s1 = Qs[t * 65 + l + 32] * scale;

                unsigned k0 = okey(s0), k1 = okey(s1);
                unsigned kmx = __reduce_max_sync(0xffffffffu, k0 > k1 ? k0 : k1);
                float mx = dekey(kmx);
                unsigned b0 = __ballot_sync(0xffffffffu, k0 == kmx);
                unsigned b1 = __ballot_sync(0xffffffffu, k1 == kmx);
                int mi = b0 ? (__ffs(b0) - 1) : (__ffs(b1) + 31);

                float e0 = __expf(s0 - mx), e1 = __expf(s1 - mx);
                esm[l] = e0; esm[l + 32] = e1;

                float pe = e0 + e1;
                float pd = e0 * R0 + e1 * R1;
                #pragma unroll
                for (int o = 16; o > 0; o >>= 1) {
                    pe += __shfl_xor_sync(0xffffffffu, pe, o);
                    pd += __shfl_xor_sync(0xffffffffu, pd, o);
                }
                float inv = 1.f / pe;
                float mdot = pd * inv;

                float4 hdt = sHd[t];
                float gg = 1.f / (1.f + __expf(-(hdt.x + mdot + bnm)));
                float wg = 1.f / (1.f + __expf(-(hdt.z + gg * wwgg + bwg)));
                wg = fminf(wg, 0.2f) * hdt.w;

                __syncwarp();

                bet[t * Sq + l]      = e0 * inv * A0;
                bet[t * Sq + l + 32] = e1 * inv * A1;
                #pragma unroll
                for (int q = 0; q < 4; ++q) {
                    int j = l + 32 * q;
                    float gv = 0.f;
                    if (j < t) {
                        int ix = idxS[j];
                        gv = esm[ix] * inv * (rS[j] * Asm[ix]);
                    }
                    gam[t * Cq + j] = gv;
                }
                __syncwarp();

                float dec = 1.f - wg;
                if (mi == l) {
                    A0 *= dec;
                    R0 = fmaf(dec, R0, wg * hdt.y);
                    Asm[mi] = A0;
                    rS[t] = wg / A0;
                    idxS[t] = mi;
                    mskS[mi * 4 + (t >> 5)] |= 1u << (t & 31);
                } else if (mi == l + 32) {
                    A1 *= dec;
                    R1 = fmaf(dec, R1, wg * hdt.y);
                    Asm[mi] = A1;
                    rS[t] = wg / A1;
                    idxS[t] = mi;
                    mskS[mi * 4 + (t >> 5)] |= 1u << (t & 31);
                }
                {
                    float v;
                    v = Qs[l * 65 + mi];
                    Qs[l * 65 + mi] = fmaf(dec, v, wg * gc0);
                    v = Qs[(l + 32) * 65 + mi];
                    Qs[(l + 32) * 65 + mi] = fmaf(dec, v, wg * gc1);
                    v = Qs[(l + 64) * 65 + mi];
                    Qs[(l + 64) * 65 + mi] = fmaf(dec, v, wg * gc2);
                    v = Qs[(l + 96) * 65 + mi];
                    Qs[(l + 96) * 65 + mi] = fmaf(dec, v, wg * gc3);
                }
                __syncwarp();
                gc0 = gn0; gc1 = gn1; gc2 = gn2; gc3 = gn3;
            }

            // epilogue: publish state for launch c+1
            g_u[b][l] = R0; g_u[b][l + 32] = R1;
            g_afinC[c][b][l] = A0; g_afinC[c][b][l + 32] = A1;
            #pragma unroll
            for (int q = 0; q < 4; ++q) {
                int j = l + 32 * q;
                int ix = idxS[j];
                g_kapC[c][b][j] = rS[j] * Asm[ix];
                g_idxC[c][b][j] = ix;
            }
        }
        __syncthreads();
        ((unsigned*)&g_mskC[c][b][0][0])[tid] = mskS[tid];
    } else {
        // -------- B path: build B_c from scan(c-1); P0(c) = H_{c+1}.B_c --------
        if (c == 0) return;
        const int id = blockIdx.x - 8;
        const int b = id >> 4, s0 = (id & 15) * 4;

        float*    kap2 = sm;                     // [128]
        float*    af4  = sm + 128;               // [4]
        unsigned* msk4 = (unsigned*)(sm + 132);  // [16]
        float*    Bsm  = sm + 160;               // 4*896 floats

        if (tid < Cq) kap2[tid] = g_kapC[c - 1][b][tid];
        if (tid < 4)  af4[tid] = g_afinC[c - 1][b][s0 + tid];
        if (tid < 16) msk4[tid] = ((unsigned*)&g_mskC[c - 1][b][s0][0])[tid];
        __syncthreads();

        const float* Hp = h + ((size_t)b * Tq + (c - 1) * Cq) * Dq;
        if (tid < 224) {
            #pragma unroll
            for (int k = 0; k < 4; ++k) {
                const int s = s0 + k;
                float4 v = ((const float4*)&g_Ball[c - 1][b][s][0])[tid];
                const float as = af4[k];
                v.x *= as; v.y *= as; v.z *= as; v.w *= as;
                #pragma unroll
                for (int w2 = 0; w2 < 4; ++w2) {
                    unsigned wd = msk4[k * 4 + w2];
                    while (wd) {
                        int bp = __ffs(wd) - 1; wd &= wd - 1;
                        int j = w2 * 32 + bp;
                        float kj = kap2[j];
                        float4 hv = ((const float4*)(Hp + (size_t)j * Dq))[tid];
                        v.x = fmaf(kj, hv.x, v.x); v.y = fmaf(kj, hv.y, v.y);
                        v.z = fmaf(kj, hv.z, v.z); v.w = fmaf(kj, hv.w, v.w);
                    }
                }
                ((float4*)&g_Ball[c][b][s][0])[tid] = v;
                ((float4*)&Bsm[k * Dq])[tid] = v;
            }
        }
        __syncthreads();

        if (c < NCq - 1) {
            const int t = tid >> 1, sp = (tid & 1) * 2;
            const float4* Hn = (const float4*)(h + ((size_t)b * Tq + (c + 1) * Cq + t) * Dq);
            const float4* Ba = (const float4*)&Bsm[(sp + 0) * Dq];
            const float4* Bb = (const float4*)&Bsm[(sp + 1) * Dq];
            float a0 = 0.f, a1 = 0.f;
            #pragma unroll 4
            for (int k = 0; k < Dq / 4; ++k) {
                float4 hv = Hn[k];
                float4 x = Ba[k];
                a0 += hv.x * x.x + hv.y * x.y + hv.z * x.z + hv.w * x.w;
                float4 y = Bb[k];
                a1 += hv.x * y.x + hv.y * y.y + hv.z * y.z + hv.w * y.w;
            }
            g_P0[b][t][s0 + sp + 0] = a0;
            g_P0[b][t][s0 + sp + 1] = a1;
        }
    }
}

// ---------------------------------------------------------------------
// m-build over ALL chunks: m = [beta|gamma] @ [B_c ; H_c]
// ---------------------------------------------------------------------
__global__ __launch_bounds__(256) void mbuild_kernel(const float* __restrict__ h)
{
    __shared__ float As2[8][128];
    __shared__ float Bs[8][128];

    const int cc = blockIdx.x / 56;
    const int r  = blockIdx.x % 56;
    const int b  = r / 7;
    const int n0 = (r % 7) * 128;
    const int t0 = cc * Cq;
    const int tid = threadIdx.x;

    const float* Bold = &g_Ball[cc][b][0][0];
    const float* Hc = h + ((size_t)b * Tq + t0) * Dq;
    const float* bet = &g_beta[b][cc][0][0];
    const float* gam = &g_gamma[b][cc][0][0];

    const int tr = tid >> 4, tc = tid & 15;
    const int lr = tid >> 1, lk = (tid & 1) * 4;
    const int kr = tid >> 5, nc = (tid & 31) * 4;

    float acc[8][8];
    #pragma unroll
    for (int i = 0; i < 8; ++i)
        #pragma unroll
        for (int j = 0; j < 8; ++j) acc[i][j] = 0.f;

    for (int k0 = 0; k0 < Sq + Cq; k0 += 8) {
        float4 av = (k0 < Sq)
            ? *(const float4*)(bet + lr * Sq + k0 + lk)
            : *(const float4*)(gam + lr * Cq + k0 - Sq + lk);
        int kg = k0 + kr;
        const float* rp = (kg < Sq) ? (Bold + (size_t)kg * Dq)
                                    : (Hc + (size_t)(kg - Sq) * Dq);
        float4 bv = *(const float4*)(rp + n0 + nc);
        __syncthreads();
        As2[lk + 0][lr] = av.x; As2[lk + 1][lr] = av.y;
        As2[lk + 2][lr] = av.z; As2[lk + 3][lr] = av.w;
        Bs[kr][nc + 0] = bv.x; Bs[kr][nc + 1] = bv.y;
        Bs[kr][nc + 2] = bv.z; Bs[kr][nc + 3] = bv.w;
        __syncthreads();
        #pragma unroll
        for (int kk = 0; kk < 8; ++kk) {
            float a[8], bb[8];
            #pragma unroll
            for (int i = 0; i < 8; ++i) a[i]  = As2[kk][tr + 16 * i];
            #pragma unroll
            for (int j = 0; j < 8; ++j) bb[j] = Bs[kk][tc + 16 * j];
            #pragma unroll
            for (int i = 0; i < 8; ++i)
                #pragma unroll
                for (int j = 0; j < 8; ++j)
                    acc[i][j] = fmaf(a[i], bb[j], acc[i][j]);
        }
    }
    #pragma unroll
    for (int i = 0; i < 8; ++i) {
        size_t row = (size_t)b * Tq + t0 + tr + 16 * i;
        #pragma unroll
        for (int j = 0; j < 8; ++j)
            g_m[row * Dq + n0 + tc + 16 * j] = acc[i][j];
    }
}

// ---------------------------------------------------------------------
__global__ __launch_bounds__(256) void stats_kernel() {
    int row = blockIdx.x * 8 + (threadIdx.x >> 5);
    int l = threadIdx.x & 31;
    const float* mr = g_m + (size_t)row * Dq;
    float s = 0.f, s2 = 0.f;
    for (int d = l; d < Dq; d += 32) { float v = mr[d]; s += v; s2 += v * v; }
    #pragma unroll
    for (int o = 16; o > 0; o >>= 1) {
        s  += __shfl_xor_sync(0xffffffffu, s, o);
        s2 += __shfl_xor_sync(0xffffffffu, s2, o);
    }
    if (l == 0) {
        float mu = s * (1.f / (float)Dq);
        float var = s2 * (1.f / (float)Dq) - mu * mu;
        g_stats[row][0] = mu;
        g_stats[row][1] = rsqrtf(var + 1e-5f);
    }
}

// ---------------------------------------------------------------------
__global__ __launch_bounds__(256) void gemm_kernel(
    const float* __restrict__ Wt,
    const float* __restrict__ H,
    const float* __restrict__ lng,
    const float* __restrict__ lnb,
    float* __restrict__ C)
{
    __shared__ float As[8][128];
    __shared__ float Bs[8][128];

    const int bm = blockIdx.y * 128;
    const int bn = blockIdx.x * 128;
    const int tid = threadIdx.x;
    const int tr = tid >> 4, tc = tid & 15;
    const int lr = tid >> 1, lk = (tid & 1) * 4;

    const float* Ap = g_m + (size_t)(bm + lr) * GK + lk;
    const float* Bp = Wt  + (size_t)(bn + lr) * GK + lk;
    const float mu = g_stats[bm + lr][0];
    const float rs = g_stats[bm + lr][1];

    float acc[8][8];
    #pragma unroll
    for (int i = 0; i < 8; ++i)
        #pragma unroll
        for (int j = 0; j < 8; ++j) acc[i][j] = 0.f;

    float4 av = *(const float4*)(Ap);
    float4 bv = *(const float4*)(Bp);

    for (int k0 = 0; k0 < GK; k0 += 8) {
        float4 gv = *(const float4*)(lng + k0 + lk);
        float4 ov = *(const float4*)(lnb + k0 + lk);
        float4 an;
        an.x = (av.x - mu) * rs * gv.x + ov.x;
        an.y = (av.y - mu) * rs * gv.y + ov.y;
        an.z = (av.z - mu) * rs * gv.z + ov.z;
        an.w = (av.w - mu) * rs * gv.w + ov.w;
        __syncthreads();
        As[lk + 0][lr] = an.x; As[lk + 1][lr] = an.y;
        As[lk + 2][lr] = an.z; As[lk + 3][lr] = an.w;
        Bs[lk + 0][lr] = bv.x; Bs[lk + 1][lr] = bv.y;
        Bs[lk + 2][lr] = bv.z; Bs[lk + 3][lr] = bv.w;
        __syncthreads();
        if (k0 + 8 < GK) {
            av = *(const float4*)(Ap + k0 + 8);
            bv = *(const float4*)(Bp + k0 + 8);
        }
        #pragma unroll
        for (int kk = 0; kk < 8; ++kk) {
            float a[8], bb[8];
            #pragma unroll
            for (int i = 0; i < 8; ++i) a[i]  = As[kk][tr + 16 * i];
            #pragma unroll
            for (int j = 0; j < 8; ++j) bb[j] = Bs[kk][tc + 16 * j];
            #pragma unroll
            for (int i = 0; i < 8; ++i)
                #pragma unroll
                for (int j = 0; j < 8; ++j)
                    acc[i][j] = fmaf(a[i], bb[j], acc[i][j]);
        }
    }

    #pragma unroll
    for (int i = 0; i < 8; ++i) {
        int m = bm + tr + 16 * i;
        #pragma unroll
        for (int j = 0; j < 8; ++j) {
            int n = bn + tc + 16 * j;
            float d2 = fminf(fmaxf(acc[i][j] * 0.5f, -2.f), 2.f);
            C[(size_t)m * GN + n] = H[(size_t)m * GN + n] + d2;
        }
    }
}

// ---------------------------------------------------------------------
extern "C" void kernel_launch(void* const* d_in, const int* in_sizes, int n_in,
                              void* d_out, int out_size) {
    const float* h    = (const float*)d_in[0];
    const int*   mask = (const int*)  d_in[1];
    const float* lng  = (const float*)d_in[2];
    const float* lnb  = (const float*)d_in[3];
    const float* Wout = (const float*)d_in[4];
    const float* Wnm  = (const float*)d_in[5];
    const float* bnm  = (const float*)d_in[6];
    const float* Wwg  = (const float*)d_in[7];
    const float* bwg  = (const float*)d_in[8];
    float* out = (float*)d_out;

    cudaFuncSetAttribute(chunk_kernel,
                         cudaFuncAttributeMaxDynamicSharedMemorySize,
                         SMEM_BYTES);

    init_kernel<<<448, 256>>>();
    pre_kernel<<<Bq * NCq + Bq * (NCq - 1), 256>>>(h, Wnm, Wwg);

    for (int c = 0; c < NCq; ++c)
        chunk_kernel<<<136, 256, SMEM_BYTES>>>(h, mask, bnm, Wwg, bwg, c);

    mbuild_kernel<<<NCq * 56, 256>>>(h);
    stats_kernel<<<GM / 8, 256>>>();

    dim3 grid(GN / 128, GM / 128);
    gemm_kernel<<<grid, 256>>>(Wout, h, lng, lnb, out);
}

// round 8
// speedup vs baseline: 2.2442x; 1.1160x over previous
#include <cuda_runtime.h>
#include <math.h>

#define Bq 8
#define Tq 4096
#define Dq 896
#define Sq 64
#define Cq 128
#define NCq 32

#define GM (Bq*Tq)
#define GN Dq
#define GK Dq

// ---------------- global scratch ----------------
__device__ float g_G[Bq][NCq][Cq][Cq];        // self grams H_c H_c^T
__device__ float g_Gx[Bq][NCq][Cq][Cq];       // cross grams H_{c+1} H_c^T
__device__ float g_hd[Bq][Tq][4];             // h.Wnm_h, h.Wnm_m, h.Wwg_h, pad
__device__ float g_Ball[NCq][Bq][Sq][Dq];     // base memory at start of each chunk
__device__ float g_P0[Bq][Cq][Sq];            // h_{c+1,t} . B_c[s]
__device__ float g_u[Bq][Sq];                 // mem[s] . Wnm_m at chunk start
__device__ float g_beta[Bq][NCq][Cq][Sq];
__device__ float g_gamma[Bq][NCq][Cq][Cq];
__device__ float g_afinC[NCq][Bq][Sq];
__device__ float g_kapC[NCq][Bq][Cq];
__device__ int   g_idxC[NCq][Bq][Cq];
__device__ unsigned g_mskC[NCq][Bq][Sq][4];
__device__ float g_E[Bq][NCq][Cq][Sq];        // softmax numerators per step (8.4MB)
__device__ float g_invA[Bq][NCq][Cq];
__device__ float g_wgA[Bq][NCq][Cq];
__device__ int   g_miA[Bq][NCq][Cq];
__device__ float g_m[(size_t)Bq*Tq*Dq];
__device__ float g_stats[(size_t)Bq*Tq][2];

// smem layout (float offsets) for chunk_kernel scan blocks
#define OF_Q    0                  // 128*65 = 8320
#define OF_G    8320               // 16384
#define OF_GX   24704              // 16384
#define OF_HD   41088              // 512 (float4[128])
#define OF_A    41600              // 64
#define OF_R    41664              // 128
#define OF_IDX  41792              // 128 (int)
#define OF_MSK  41920              // 256 (uint 64x4)
#define OF_KF   42176              // 128
#define SMEM_FLOATS 42304
#define SMEM_BYTES (SMEM_FLOATS*4)

// recon kernel smem layout (floats)
#define RS_E    0                  // 8192
#define RS_A    8192               // 8192
#define RS_R    16384              // 128
#define RS_INV  16512              // 128
#define RS_WG   16640              // 128
#define RS_MI   16768              // 128 (int)
#define RSMEM_FLOATS 16896
#define RSMEM_BYTES (RSMEM_FLOATS*4)

__device__ __forceinline__ unsigned okey(float f) {
    unsigned u = __float_as_uint(f);
    return (u & 0x80000000u) ? ~u : (u | 0x80000000u);
}
__device__ __forceinline__ float dekey(unsigned k) {
    unsigned u = (k & 0x80000000u) ? (k ^ 0x80000000u) : ~k;
    return __uint_as_float(u);
}

// ---------------------------------------------------------------------
__global__ void init_kernel() {
    int tid = blockIdx.x * blockDim.x + threadIdx.x;
    int stride = gridDim.x * blockDim.x;
    int nb = Bq * Sq * Dq;
    for (int i = tid; i < nb; i += stride) (&g_Ball[0][0][0][0])[i] = 0.f;
    int np = Bq * Cq * Sq;
    for (int i = tid; i < np; i += stride) (&g_P0[0][0][0])[i] = 0.f;
    if (tid < Bq * Sq) (&g_u[0][0])[tid] = 0.f;
}

// ---------------------------------------------------------------------
// pre: blocks [0,256): G[b][c] = Hc Hc^T (+ h-dot vectors)
//      blocks [256,504): Gx[b][c] = H_{c+1} Hc^T
// ---------------------------------------------------------------------
__global__ __launch_bounds__(256) void pre_kernel(
    const float* __restrict__ h,
    const float* __restrict__ W_nm,
    const float* __restrict__ W_wg)
{
    __shared__ float As[8][128];
    __shared__ float Bs[8][128];

    const int tid = threadIdx.x;
    const int tr = tid >> 4, tc = tid & 15;
    const int lr = tid >> 1, lk = (tid & 1) * 4;

    int b, c;
    const float *Arow, *Brow;
    float* outp;
    bool doHd;
    if (blockIdx.x < Bq * NCq) {
        b = blockIdx.x / NCq; c = blockIdx.x % NCq;
        Arow = h + ((size_t)b * Tq + c * Cq) * Dq;
        Brow = Arow;
        outp = &g_G[b][c][0][0];
        doHd = true;
    } else {
        int k = blockIdx.x - Bq * NCq;
        b = k / (NCq - 1); c = k % (NCq - 1);
        Arow = h + ((size_t)b * Tq + (c + 1) * Cq) * Dq;
        Brow = h + ((size_t)b * Tq + c * Cq) * Dq;
        outp = &g_Gx[b][c][0][0];
        doHd = false;
    }

    float acc[8][8];
    #pragma unroll
    for (int i = 0; i < 8; ++i)
        #pragma unroll
        for (int j = 0; j < 8; ++j) acc[i][j] = 0.f;

    float4 av = *(const float4*)(Arow + (size_t)lr * Dq + lk);
    float4 bv = *(const float4*)(Brow + (size_t)lr * Dq + lk);
    for (int k0 = 0; k0 < Dq; k0 += 8) {
        __syncthreads();
        As[lk + 0][lr] = av.x; As[lk + 1][lr] = av.y;
        As[lk + 2][lr] = av.z; As[lk + 3][lr] = av.w;
        Bs[lk + 0][lr] = bv.x; Bs[lk + 1][lr] = bv.y;
        Bs[lk + 2][lr] = bv.z; Bs[lk + 3][lr] = bv.w;
        __syncthreads();
        if (k0 + 8 < Dq) {
            av = *(const float4*)(Arow + (size_t)lr * Dq + k0 + 8 + lk);
            bv = *(const float4*)(Brow + (size_t)lr * Dq + k0 + 8 + lk);
        }
        #pragma unroll
        for (int kk = 0; kk < 8; ++kk) {
            float a[8], bb[8];
            #pragma unroll
            for (int i = 0; i < 8; ++i) a[i]  = As[kk][tr + 16 * i];
            #pragma unroll
            for (int j = 0; j < 8; ++j) bb[j] = Bs[kk][tc + 16 * j];
            #pragma unroll
            for (int i = 0; i < 8; ++i)
                #pragma unroll
                for (int j = 0; j < 8; ++j)
                    acc[i][j] = fmaf(a[i], bb[j], acc[i][j]);
        }
    }
    #pragma unroll
    for (int i = 0; i < 8; ++i)
        #pragma unroll
        for (int j = 0; j < 8; ++j)
            outp[(tr + 16 * i) * Cq + tc + 16 * j] = acc[i][j];

    if (doHd) {
        const int w = tid >> 5, l = tid & 31;
        const int t0 = c * Cq;
        for (int r = w; r < Cq; r += 8) {
            const float* hr = Arow + (size_t)r * Dq;
            float s0 = 0.f, s1 = 0.f, s2 = 0.f;
            for (int d = l; d < Dq; d += 32) {
                float x = hr[d];
                s0 += x * W_nm[d];
                s1 += x * W_nm[Dq + d];
                s2 += x * W_wg[d];
            }
            #pragma unroll
            for (int o = 16; o > 0; o >>= 1) {
                s0 += __shfl_xor_sync(0xffffffffu, s0, o);
                s1 += __shfl_xor_sync(0xffffffffu, s1, o);
                s2 += __shfl_xor_sync(0xffffffffu, s2, o);
            }
            if (l == 0) {
                g_hd[b][t0 + r][0] = s0;
                g_hd[b][t0 + r][1] = s1;
                g_hd[b][t0 + r][2] = s2;
                g_hd[b][t0 + r][3] = 0.f;
            }
        }
    }
}

// ---------------------------------------------------------------------
// chunk launch c:
//   blocks 0..7    : fixup(Q) then minimal scan(c) (records E/inv/wg/mi)
//   blocks 8..135  : build B_c from scan(c-1); P0(c) = H_{c+1}.B_c
// ---------------------------------------------------------------------
__global__ __launch_bounds__(256) void chunk_kernel(
    const float* __restrict__ h, const int* __restrict__ mask,
    const float* __restrict__ b_nm, const float* __restrict__ W_wg,
    const float* __restrict__ b_wg, int c)
{
    extern __shared__ float sm[];
    const int tid = threadIdx.x;

    if (blockIdx.x < 8) {
        float*    Qs   = sm + OF_Q;     // [128][65]
        float*    sG   = sm + OF_G;     // [128][128]
        float*    sGx  = sm + OF_GX;    // [128][128]
        float4*   sHd  = (float4*)(sm + OF_HD);
        float*    Asm  = sm + OF_A;
        float*    rS   = sm + OF_R;
        int*      idxS = (int*)(sm + OF_IDX);
        unsigned* mskS = (unsigned*)(sm + OF_MSK);
        float*    kapF = sm + OF_KF;

        const int b = blockIdx.x;
        const int t0 = c * Cq;

        // ---- stage ----
        if (tid < Cq) {
            float4 hv = ((const float4*)g_hd)[(size_t)b * Tq + t0 + tid];
            hv.w = (float)mask[b * Tq + t0 + tid];
            sHd[tid] = hv;
        }
        {
            const float4* gsrc = (const float4*)&g_G[b][c][0][0];
            #pragma unroll 4
            for (int i = tid; i < Cq * Cq / 4; i += 256)
                ((float4*)sG)[i] = gsrc[i];
        }
        if (c > 0) {
            const float4* xsrc = (const float4*)&g_Gx[b][c - 1][0][0];
            #pragma unroll 4
            for (int i = tid; i < Cq * Cq / 4; i += 256)
                ((float4*)sGx)[i] = xsrc[i];
            if (tid < Sq) Asm[tid] = g_afinC[c - 1][b][tid];
            if (tid < Cq) {
                kapF[tid] = g_kapC[c - 1][b][tid];
                idxS[tid] = g_idxC[c - 1][b][tid];
            }
        }
        __syncthreads();

        // ---- fixup: Q(c) = af*P0(c-1) + sum_j kap_j * Gx[c-1] ----
        if (c == 0) {
            for (int i = tid; i < Cq * Sq; i += 256) {
                int tau = i >> 6, s = i & 63;
                Qs[tau * 65 + s] = 0.f;
            }
        } else {
            const int t = tid >> 1, hf = (tid & 1) * 32;
            const float* P0r = &g_P0[b][t][0];
            float* Qr = Qs + t * 65;
            #pragma unroll 8
            for (int q = 0; q < 32; ++q) {
                int s = hf + q;
                Qr[s] = Asm[s] * P0r[s];
            }
            const float* gxr = sGx + t * Cq;
            for (int j = 0; j < Cq; ++j) {
                int s = idxS[j];
                if ((unsigned)(s - hf) < 32u)
                    Qr[s] = fmaf(kapF[j], gxr[j], Qr[s]);
            }
        }
        __syncthreads();
        // reinit scan bookkeeping
        if (tid < Sq) Asm[tid] = 1.f;
        if (tid < Cq) { rS[tid] = 0.f; idxS[tid] = 0; }
        mskS[tid] = 0;
        __syncthreads();

        if (tid < 32) {
            // ---------------- minimal scan (warp 0) ----------------
            const int l = tid;
            const float scale = rsqrtf((float)Dq);
            const float wwgg = W_wg[Dq];
            const float bnm = b_nm[0], bwg = b_wg[0];
            float A0 = 1.f, A1 = 1.f;
            float R0 = g_u[b][l], R1 = g_u[b][l + 32];
            float* gE = &g_E[b][c][0][0];
            float* gInv = &g_invA[b][c][0];
            float* gWg  = &g_wgA[b][c][0];
            int*   gMi  = &g_miA[b][c][0];

            for (int t = 0; t < Cq; ++t) {
                // G row t (symmetric: G[tau][t] = G[t][tau]) — independent loads
                const float* gr = sG + t * Cq;
                float g0 = gr[l], g1 = gr[l + 32];
                float g2 = gr[l + 64], g3 = gr[l + 96];

                float s0 = Qs[t * 65 + l] * scale;
                float s1 = Qs[t * 65 + l + 32] * scale;

                unsigned k0 = okey(s0), k1 = okey(s1);
                unsigned kmx = __reduce_max_sync(0xffffffffu, k0 > k1 ? k0 : k1);
                float mx = dekey(kmx);
                unsigned b0 = __ballot_sync(0xffffffffu, k0 == kmx);
                unsigned b1 = __ballot_sync(0xffffffffu, k1 == kmx);
                int mi = b0 ? (__ffs(b0) - 1) : (__ffs(b1) + 31);

                float e0 = __expf(s0 - mx), e1 = __expf(s1 - mx);
                gE[t * Sq + l] = e0;           // fire-and-forget records
                gE[t * Sq + l + 32] = e1;

                float pe = e0 + e1;
                float pd = e0 * R0 + e1 * R1;
                #pragma unroll
                for (int o = 16; o > 0; o >>= 1) {
                    pe += __shfl_xor_sync(0xffffffffu, pe, o);
                    pd += __shfl_xor_sync(0xffffffffu, pd, o);
                }
                float inv = __fdividef(1.f, pe);
                float mdot = pd * inv;

                float4 hdt = sHd[t];
                float gg = __fdividef(1.f, 1.f + __expf(-(hdt.x + mdot + bnm)));
                float wg = __fdividef(1.f, 1.f + __expf(-(hdt.z + gg * wwgg + bwg)));
                wg = fminf(wg, 0.2f) * hdt.w;

                if (l == 0) gInv[t] = inv;
                if (l == 1) gWg[t] = wg;
                if (l == 2) gMi[t] = mi;

                float dec = 1.f - wg;
                if (mi == l) {
                    A0 *= dec;
                    R0 = fmaf(dec, R0, wg * hdt.y);
                    Asm[mi] = A0;
                    rS[t] = wg / A0;
                    idxS[t] = mi;
                    mskS[mi * 4 + (t >> 5)] |= 1u << (t & 31);
                } else if (mi == l + 32) {
                    A1 *= dec;
                    R1 = fmaf(dec, R1, wg * hdt.y);
                    Asm[mi] = A1;
                    rS[t] = wg / A1;
                    idxS[t] = mi;
                    mskS[mi * 4 + (t >> 5)] |= 1u << (t & 31);
                }
                {
                    float v;
                    v = Qs[l * 65 + mi];
                    Qs[l * 65 + mi] = fmaf(dec, v, wg * g0);
                    v = Qs[(l + 32) * 65 + mi];
                    Qs[(l + 32) * 65 + mi] = fmaf(dec, v, wg * g1);
                    v = Qs[(l + 64) * 65 + mi];
                    Qs[(l + 64) * 65 + mi] = fmaf(dec, v, wg * g2);
                    v = Qs[(l + 96) * 65 + mi];
                    Qs[(l + 96) * 65 + mi] = fmaf(dec, v, wg * g3);
                }
                __syncwarp();
            }

            // epilogue: publish state for launch c+1
            g_u[b][l] = R0; g_u[b][l + 32] = R1;
            g_afinC[c][b][l] = A0; g_afinC[c][b][l + 32] = A1;
            #pragma unroll
            for (int q = 0; q < 4; ++q) {
                int j = l + 32 * q;
                int ix = idxS[j];
                g_kapC[c][b][j] = rS[j] * Asm[ix];
                g_idxC[c][b][j] = ix;
            }
        }
        __syncthreads();
        ((unsigned*)&g_mskC[c][b][0][0])[tid] = mskS[tid];
    } else {
        // -------- B path: build B_c from scan(c-1); P0(c) = H_{c+1}.B_c --------
        if (c == 0) return;
        const int id = blockIdx.x - 8;
        const int b = id >> 4, s0 = (id & 15) * 4;

        float*    kap2 = sm;                     // [128]
        float*    af4  = sm + 128;               // [4]
        unsigned* msk4 = (unsigned*)(sm + 132);  // [16]
        float*    Bsm  = sm + 160;               // 4*896 floats

        if (tid < Cq) kap2[tid] = g_kapC[c - 1][b][tid];
        if (tid < 4)  af4[tid] = g_afinC[c - 1][b][s0 + tid];
        if (tid < 16) msk4[tid] = ((unsigned*)&g_mskC[c - 1][b][s0][0])[tid];
        __syncthreads();

        const float* Hp = h + ((size_t)b * Tq + (c - 1) * Cq) * Dq;
        if (tid < 224) {
            #pragma unroll
            for (int k = 0; k < 4; ++k) {
                const int s = s0 + k;
                float4 v = ((const float4*)&g_Ball[c - 1][b][s][0])[tid];
                const float as = af4[k];
                v.x *= as; v.y *= as; v.z *= as; v.w *= as;
                #pragma unroll
                for (int w2 = 0; w2 < 4; ++w2) {
                    unsigned wd = msk4[k * 4 + w2];
                    while (wd) {
                        int bp = __ffs(wd) - 1; wd &= wd - 1;
                        int j = w2 * 32 + bp;
                        float kj = kap2[j];
                        float4 hv = ((const float4*)(Hp + (size_t)j * Dq))[tid];
                        v.x = fmaf(kj, hv.x, v.x); v.y = fmaf(kj, hv.y, v.y);
                        v.z = fmaf(kj, hv.z, v.z); v.w = fmaf(kj, hv.w, v.w);
                    }
                }
                ((float4*)&g_Ball[c][b][s][0])[tid] = v;
                ((float4*)&Bsm[k * Dq])[tid] = v;
            }
        }
        __syncthreads();

        if (c < NCq - 1) {
            const int t = tid >> 1, sp = (tid & 1) * 2;
            const float4* Hn = (const float4*)(h + ((size_t)b * Tq + (c + 1) * Cq + t) * Dq);
            const float4* Ba = (const float4*)&Bsm[(sp + 0) * Dq];
            const float4* Bb = (const float4*)&Bsm[(sp + 1) * Dq];
            float a0 = 0.f, a1 = 0.f;
            #pragma unroll 4
            for (int k = 0; k < Dq / 4; ++k) {
                float4 hv = Hn[k];
                float4 x = Ba[k];
                a0 += hv.x * x.x + hv.y * x.y + hv.z * x.z + hv.w * x.w;
                float4 y = Bb[k];
                a1 += hv.x * y.x + hv.y * y.y + hv.z * y.z + hv.w * y.w;
            }
            g_P0[b][t][s0 + sp + 0] = a0;
            g_P0[b][t][s0 + sp + 1] = a1;
        }
    }
}

// ---------------------------------------------------------------------
// recon: rebuild beta/gamma for all (b,c) from (E, inv, wg, mi) records
// ---------------------------------------------------------------------
__global__ __launch_bounds__(256) void recon_kernel() {
    extern __shared__ float rs[];
    float* sE   = rs + RS_E;
    float* sA   = rs + RS_A;
    float* sr   = rs + RS_R;
    float* sinv = rs + RS_INV;
    float* swg  = rs + RS_WG;
    int*   smi  = (int*)(rs + RS_MI);

    const int b = blockIdx.x >> 5;
    const int c = blockIdx.x & 31;
    const int tid = threadIdx.x;

    const float4* esrc = (const float4*)&g_E[b][c][0][0];
    #pragma unroll 4
    for (int i = tid; i < Cq * Sq / 4; i += 256) ((float4*)sE)[i] = esrc[i];
    if (tid < Cq) {
        sinv[tid] = g_invA[b][c][tid];
        swg[tid]  = g_wgA[b][c][tid];
        smi[tid]  = g_miA[b][c][tid];
    }
    __syncthreads();

    if (tid < Sq) {
        float A = 1.f;
        for (int t = 0; t < Cq; ++t) {
            sA[t * Sq + tid] = A;
            if (smi[t] == tid) {
                A *= (1.f - swg[t]);
                sr[t] = swg[t] / A;
            }
        }
    }
    __syncthreads();

    float* bet = &g_beta[b][c][0][0];
    for (int i = tid; i < Cq * Sq; i += 256) {
        int t = i >> 6;
        bet[i] = sE[i] * sinv[t] * sA[i];
    }
    float* gam = &g_gamma[b][c][0][0];
    for (int i = tid; i < Cq * Cq; i += 256) {
        int t = i >> 7, j = i & 127;
        float gv = 0.f;
        if (j < t) {
            int ix = smi[j];
            gv = sE[t * Sq + ix] * sinv[t] * sr[j] * sA[t * Sq + ix];
        }
        gam[i] = gv;
    }
}

// ---------------------------------------------------------------------
// m-build over ALL chunks: m = [beta|gamma] @ [B_c ; H_c]
// ---------------------------------------------------------------------
__global__ __launch_bounds__(256) void mbuild_kernel(const float* __restrict__ h)
{
    __shared__ float As2[8][128];
    __shared__ float Bs[8][128];

    const int cc = blockIdx.x / 56;
    const int r  = blockIdx.x % 56;
    const int b  = r / 7;
    const int n0 = (r % 7) * 128;
    const int t0 = cc * Cq;
    const int tid = threadIdx.x;

    const float* Bold = &g_Ball[cc][b][0][0];
    const float* Hc = h + ((size_t)b * Tq + t0) * Dq;
    const float* bet = &g_beta[b][cc][0][0];
    const float* gam = &g_gamma[b][cc][0][0];

    const int tr = tid >> 4, tc = tid & 15;
    const int lr = tid >> 1, lk = (tid & 1) * 4;
    const int kr = tid >> 5, nc = (tid & 31) * 4;

    float acc[8][8];
    #pragma unroll
    for (int i = 0; i < 8; ++i)
        #pragma unroll
        for (int j = 0; j < 8; ++j) acc[i][j] = 0.f;

    for (int k0 = 0; k0 < Sq + Cq; k0 += 8) {
        float4 av = (k0 < Sq)
            ? *(const float4*)(bet + lr * Sq + k0 + lk)
            : *(const float4*)(gam + lr * Cq + k0 - Sq + lk);
        int kg = k0 + kr;
        const float* rp = (kg < Sq) ? (Bold + (size_t)kg * Dq)
                                    : (Hc + (size_t)(kg - Sq) * Dq);
        float4 bv = *(const float4*)(rp + n0 + nc);
        __syncthreads();
        As2[lk + 0][lr] = av.x; As2[lk + 1][lr] = av.y;
        As2[lk + 2][lr] = av.z; As2[lk + 3][lr] = av.w;
        Bs[kr][nc + 0] = bv.x; Bs[kr][nc + 1] = bv.y;
        Bs[kr][nc + 2] = bv.z; Bs[kr][nc + 3] = bv.w;
        __syncthreads();
        #pragma unroll
        for (int kk = 0; kk < 8; ++kk) {
            float a[8], bb[8];
            #pragma unroll
            for (int i = 0; i < 8; ++i) a[i]  = As2[kk][tr + 16 * i];
            #pragma unroll
            for (int j = 0; j < 8; ++j) bb[j] = Bs[kk][tc + 16 * j];
            #pragma unroll
            for (int i = 0; i < 8; ++i)
                #pragma unroll
                for (int j = 0; j < 8; ++j)
                    acc[i][j] = fmaf(a[i], bb[j], acc[i][j]);
        }
    }
    #pragma unroll
    for (int i = 0; i < 8; ++i) {
        size_t row = (size_t)b * Tq + t0 + tr + 16 * i;
        #pragma unroll
        for (int j = 0; j < 8; ++j)
            g_m[row * Dq + n0 + tc + 16 * j] = acc[i][j];
    }
}

// ---------------------------------------------------------------------
__global__ __launch_bounds__(256) void stats_kernel() {
    int row = blockIdx.x * 8 + (threadIdx.x >> 5);
    int l = threadIdx.x & 31;
    const float* mr = g_m + (size_t)row * Dq;
    float s = 0.f, s2 = 0.f;
    for (int d = l; d < Dq; d += 32) { float v = mr[d]; s += v; s2 += v * v; }
    #pragma unroll
    for (int o = 16; o > 0; o >>= 1) {
        s  += __shfl_xor_sync(0xffffffffu, s, o);
        s2 += __shfl_xor_sync(0xffffffffu, s2, o);
    }
    if (l == 0) {
        float mu = s * (1.f / (float)Dq);
        float var = s2 * (1.f / (float)Dq) - mu * mu;
        g_stats[row][0] = mu;
        g_stats[row][1] = rsqrtf(var + 1e-5f);
    }
}

// ---------------------------------------------------------------------
__global__ __launch_bounds__(256) void gemm_kernel(
    const float* __restrict__ Wt,
    const float* __restrict__ H,
    const float* __restrict__ lng,
    const float* __restrict__ lnb,
    float* __restrict__ C)
{
    __shared__ float As[8][128];
    __shared__ float Bs[8][128];

    const int bm = blockIdx.y * 128;
    const int bn = blockIdx.x * 128;
    const int tid = threadIdx.x;
    const int tr = tid >> 4, tc = tid & 15;
    const int lr = tid >> 1, lk = (tid & 1) * 4;

    const float* Ap = g_m + (size_t)(bm + lr) * GK + lk;
    const float* Bp = Wt  + (size_t)(bn + lr) * GK + lk;
    const float mu = g_stats[bm + lr][0];
    const float rs = g_stats[bm + lr][1];

    float acc[8][8];
    #pragma unroll
    for (int i = 0; i < 8; ++i)
        #pragma unroll
        for (int j = 0; j < 8; ++j) acc[i][j] = 0.f;

    float4 av = *(const float4*)(Ap);
    float4 bv = *(const float4*)(Bp);

    for (int k0 = 0; k0 < GK; k0 += 8) {
        float4 gv = *(const float4*)(lng + k0 + lk);
        float4 ov = *(const float4*)(lnb + k0 + lk);
        float4 an;
        an.x = (av.x - mu) * rs * gv.x + ov.x;
        an.y = (av.y - mu) * rs * gv.y + ov.y;
        an.z = (av.z - mu) * rs * gv.z + ov.z;
        an.w = (av.w - mu) * rs * gv.w + ov.w;
        __syncthreads();
        As[lk + 0][lr] = an.x; As[lk + 1][lr] = an.y;
        As[lk + 2][lr] = an.z; As[lk + 3][lr] = an.w;
        Bs[lk + 0][lr] = bv.x; Bs[lk + 1][lr] = bv.y;
        Bs[lk + 2][lr] = bv.z; Bs[lk + 3][lr] = bv.w;
        __syncthreads();
        if (k0 + 8 < GK) {
            av = *(const float4*)(Ap + k0 + 8);
            bv = *(const float4*)(Bp + k0 + 8);
        }
        #pragma unroll
        for (int kk = 0; kk < 8; ++kk) {
            float a[8], bb[8];
            #pragma unroll
            for (int i = 0; i < 8; ++i) a[i]  = As[kk][tr + 16 * i];
            #pragma unroll
            for (int j = 0; j < 8; ++j) bb[j] = Bs[kk][tc + 16 * j];
            #pragma unroll
            for (int i = 0; i < 8; ++i)
                #pragma unroll
                for (int j = 0; j < 8; ++j)
                    acc[i][j] = fmaf(a[i], bb[j], acc[i][j]);
        }
    }

    #pragma unroll
    for (int i = 0; i < 8; ++i) {
        int m = bm + tr + 16 * i;
        #pragma unroll
        for (int j = 0; j < 8; ++j) {
            int n = bn + tc + 16 * j;
            float d2 = fminf(fmaxf(acc[i][j] * 0.5f, -2.f), 2.f);
            C[(size_t)m * GN + n] = H[(size_t)m * GN + n] + d2;
        }
    }
}

// ---------------------------------------------------------------------
extern "C" void kernel_launch(void* const* d_in, const int* in_sizes, int n_in,
                              void* d_out, int out_size) {
    const float* h    = (const float*)d_in[0];
    const int*   mask = (const int*)  d_in[1];
    const float* lng  = (const float*)d_in[2];
    const float* lnb  = (const float*)d_in[3];
    const float* Wout = (const float*)d_in[4];
    const float* Wnm  = (const float*)d_in[5];
    const float* bnm  = (const float*)d_in[6];
    const float* Wwg  = (const float*)d_in[7];
    const float* bwg  = (const float*)d_in[8];
    float* out = (float*)d_out;

    cudaFuncSetAttribute(chunk_kernel,
                         cudaFuncAttributeMaxDynamicSharedMemorySize,
                         SMEM_BYTES);
    cudaFuncSetAttribute(recon_kernel,
                         cudaFuncAttributeMaxDynamicSharedMemorySize,
                         RSMEM_BYTES);

    init_kernel<<<448, 256>>>();
    pre_kernel<<<Bq * NCq + Bq * (NCq - 1), 256>>>(h, Wnm, Wwg);

    for (int c = 0; c < NCq; ++c)
        chunk_kernel<<<136, 256, SMEM_BYTES>>>(h, mask, bnm, Wwg, bwg, c);

    recon_kernel<<<Bq * NCq, 256, RSMEM_BYTES>>>();
    mbuild_kernel<<<NCq * 56, 256>>>(h);
    stats_kernel<<<GM / 8, 256>>>();

    dim3 grid(GN / 128, GM / 128);
    gemm_kernel<<<grid, 256>>>(Wout, h, lng, lnb, out);
}